// round 5
// baseline (speedup 1.0000x reference)
#include <cuda_runtime.h>
#include <cuda_bf16.h>
#include <cstdint>
#include <math.h>

// Problem constants
#define SEQ    2048
#define DMODEL 1024
#define NH     4
#define DHEAD  256
#define NCHUNK 64
#define CSZ    32

// ---------------- scratch (device globals; allocation-free) ----------------
__device__ __align__(16) float g_qlin[SEQ * DMODEL];
__device__ __align__(16) float g_klin[SEQ * DMODEL];
__device__ __align__(16) float g_vlin[SEQ * DMODEL];
__device__ __align__(16) float g_q[SEQ * DMODEL];
__device__ __align__(16) float g_k[SEQ * DMODEL];
__device__ __align__(16) float g_v[SEQ * DMODEL];
__device__ __align__(16) float g_u[SEQ * DMODEL];
__device__ __align__(16) float g_w[SEQ * DMODEL];
__device__ __align__(16) float g_delta[SEQ * DMODEL];
__device__ __align__(16) float g_mix[SEQ * DMODEL];
__device__ __align__(16) float g_beta[SEQ * NH];
__device__ __align__(16) float g_probs[SEQ * NH * 5];
__device__ __align__(16) float g_attn[NH * NCHUNK * CSZ * CSZ];

// bf16 hi/lo split buffers
__device__ __align__(16) __nv_bfloat16 g_xhi[SEQ * DMODEL];
__device__ __align__(16) __nv_bfloat16 g_xlo[SEQ * DMODEL];
__device__ __align__(16) __nv_bfloat16 g_wqhi[DMODEL * DMODEL];
__device__ __align__(16) __nv_bfloat16 g_wqlo[DMODEL * DMODEL];
__device__ __align__(16) __nv_bfloat16 g_wkhi[DMODEL * DMODEL];
__device__ __align__(16) __nv_bfloat16 g_wklo[DMODEL * DMODEL];
__device__ __align__(16) __nv_bfloat16 g_wvhi[DMODEL * DMODEL];
__device__ __align__(16) __nv_bfloat16 g_wvlo[DMODEL * DMODEL];
__device__ __align__(16) __nv_bfloat16 g_wohi[DMODEL * DMODEL];
__device__ __align__(16) __nv_bfloat16 g_wolo[DMODEL * DMODEL];
__device__ __align__(16) __nv_bfloat16 g_mixhi[SEQ * DMODEL];
__device__ __align__(16) __nv_bfloat16 g_mixlo[SEQ * DMODEL];

// ---------------- bf16 hi/lo tensor-core GEMM: C = A * B^T ------------------
// Block 256 thr (8 warps), tile 128x128, K-chunk 16 (one m16n8k16 step),
// 3 products (hh, hl, lh) in fp32 accum. Double-buffered smem, reg prefetch.
// smem row stride 24 bf16 (48B) -> conflict-free fragment loads.
#define HG_STRIDE_B 48          // bytes per smem row
#define HG_TILE_B   6144        // 128 rows * 48B
#define HG_BUF_B    (4 * HG_TILE_B)   // AH, AL, BH, BL
#define HG_SMEM     (2 * HG_BUF_B)    // 49152

__device__ __forceinline__ void mma_bf16(float* acc, const unsigned* a,
                                         const unsigned* b) {
    asm volatile(
        "mma.sync.aligned.m16n8k16.row.col.f32.bf16.bf16.f32 "
        "{%0,%1,%2,%3}, {%4,%5,%6,%7}, {%8,%9}, {%0,%1,%2,%3};"
        : "+f"(acc[0]), "+f"(acc[1]), "+f"(acc[2]), "+f"(acc[3])
        : "r"(a[0]), "r"(a[1]), "r"(a[2]), "r"(a[3]), "r"(b[0]), "r"(b[1]));
}

__global__ __launch_bounds__(256) void hgemm_nt(const __nv_bfloat16* __restrict__ Ahi,
                                                const __nv_bfloat16* __restrict__ Alo,
                                                const __nv_bfloat16* __restrict__ Bhi,
                                                const __nv_bfloat16* __restrict__ Blo,
                                                float* __restrict__ C,
                                                int M, int N, int K) {
    extern __shared__ __align__(16) char smem[];
    int tid = threadIdx.x;
    int warp = tid >> 5, lane = tid & 31;
    int wm = warp >> 2, wn = warp & 3;
    int g = lane >> 2, t = lane & 3;
    int bm = blockIdx.y * 128, bn = blockIdx.x * 128;

    float acc[4][4][4];
#pragma unroll
    for (int mi = 0; mi < 4; mi++)
#pragma unroll
        for (int nj = 0; nj < 4; nj++)
#pragma unroll
            for (int r = 0; r < 4; r++) acc[mi][nj][r] = 0.f;

    // loaders: thread -> (row, half): row 0..127, half 0..1 (8 bf16 = 16B)
    const int lrow = tid >> 1, lhalf = tid & 1;
    uint4 rah, ral, rbh, rbl;

#define HG_LDG(k0)                                                                 \
    do {                                                                           \
        size_t ga = (size_t)(bm + lrow) * K + (k0) + lhalf * 8;                    \
        size_t gb = (size_t)(bn + lrow) * K + (k0) + lhalf * 8;                    \
        rah = *(const uint4*)(Ahi + ga);                                           \
        ral = *(const uint4*)(Alo + ga);                                           \
        rbh = *(const uint4*)(Bhi + gb);                                           \
        rbl = *(const uint4*)(Blo + gb);                                           \
    } while (0)

#define HG_STS(buf)                                                                \
    do {                                                                           \
        char* base = smem + (buf) * HG_BUF_B + lrow * HG_STRIDE_B + lhalf * 16;    \
        *(uint4*)(base + 0 * HG_TILE_B) = rah;                                     \
        *(uint4*)(base + 1 * HG_TILE_B) = ral;                                     \
        *(uint4*)(base + 2 * HG_TILE_B) = rbh;                                     \
        *(uint4*)(base + 3 * HG_TILE_B) = rbl;                                     \
    } while (0)

    HG_LDG(0);
    HG_STS(0);
    __syncthreads();

    int nch = K / 16;
    for (int ch = 0; ch < nch; ch++) {
        int buf = ch & 1;
        if (ch + 1 < nch) HG_LDG((ch + 1) * 16);

        const char* AH = smem + buf * HG_BUF_B;
        const char* AL = AH + HG_TILE_B;
        const char* BH = AH + 2 * HG_TILE_B;
        const char* BL = AH + 3 * HG_TILE_B;

        unsigned ah[4][4], al[4][4], bh[4][2], bl[4][2];
#pragma unroll
        for (int mi = 0; mi < 4; mi++) {
            int r0 = wm * 64 + mi * 16 + g;
            ah[mi][0] = *(const unsigned*)(AH + r0 * HG_STRIDE_B + t * 4);
            ah[mi][1] = *(const unsigned*)(AH + (r0 + 8) * HG_STRIDE_B + t * 4);
            ah[mi][2] = *(const unsigned*)(AH + r0 * HG_STRIDE_B + 16 + t * 4);
            ah[mi][3] = *(const unsigned*)(AH + (r0 + 8) * HG_STRIDE_B + 16 + t * 4);
            al[mi][0] = *(const unsigned*)(AL + r0 * HG_STRIDE_B + t * 4);
            al[mi][1] = *(const unsigned*)(AL + (r0 + 8) * HG_STRIDE_B + t * 4);
            al[mi][2] = *(const unsigned*)(AL + r0 * HG_STRIDE_B + 16 + t * 4);
            al[mi][3] = *(const unsigned*)(AL + (r0 + 8) * HG_STRIDE_B + 16 + t * 4);
        }
#pragma unroll
        for (int nj = 0; nj < 4; nj++) {
            int n = wn * 32 + nj * 8 + g;
            bh[nj][0] = *(const unsigned*)(BH + n * HG_STRIDE_B + t * 4);
            bh[nj][1] = *(const unsigned*)(BH + n * HG_STRIDE_B + 16 + t * 4);
            bl[nj][0] = *(const unsigned*)(BL + n * HG_STRIDE_B + t * 4);
            bl[nj][1] = *(const unsigned*)(BL + n * HG_STRIDE_B + 16 + t * 4);
        }
#pragma unroll
        for (int mi = 0; mi < 4; mi++)
#pragma unroll
            for (int nj = 0; nj < 4; nj++) {
                mma_bf16(acc[mi][nj], ah[mi], bh[nj]);
                mma_bf16(acc[mi][nj], ah[mi], bl[nj]);
                mma_bf16(acc[mi][nj], al[mi], bh[nj]);
            }
        if (ch + 1 < nch) {
            HG_STS(buf ^ 1);
            __syncthreads();
        }
    }

#pragma unroll
    for (int mi = 0; mi < 4; mi++) {
        int row = bm + wm * 64 + mi * 16 + g;
#pragma unroll
        for (int nj = 0; nj < 4; nj++) {
            int col = bn + wn * 32 + nj * 8 + t * 2;
            *(float2*)(C + (size_t)row * N + col) =
                make_float2(acc[mi][nj][0], acc[mi][nj][1]);
            *(float2*)(C + (size_t)(row + 8) * N + col) =
                make_float2(acc[mi][nj][2], acc[mi][nj][3]);
        }
    }
#undef HG_LDG
#undef HG_STS
}

// ---------------- fp32 -> bf16 hi/lo split ---------------------------------
__global__ void split_kernel(const float* __restrict__ in,
                             __nv_bfloat16* __restrict__ hi,
                             __nv_bfloat16* __restrict__ lo, int n4) {
    int i = blockIdx.x * 256 + threadIdx.x;
    if (i >= n4) return;
    float4 v = ((const float4*)in)[i];
    float vv[4] = {v.x, v.y, v.z, v.w};
    __align__(8) __nv_bfloat16 h[4];
    __align__(8) __nv_bfloat16 l[4];
#pragma unroll
    for (int j = 0; j < 4; j++) {
        h[j] = __float2bfloat16(vv[j]);
        l[j] = __float2bfloat16(vv[j] - __bfloat162float(h[j]));
    }
    ((uint2*)hi)[i] = *(uint2*)h;
    ((uint2*)lo)[i] = *(uint2*)l;
}

// ---------------- short conv (K=4, causal) + silu --------------------------
__global__ void conv_silu_kernel(const float* __restrict__ xin,
                                 const float* __restrict__ w,
                                 float* __restrict__ out) {
    int idx = blockIdx.x * blockDim.x + threadIdx.x;
    int c = idx & (DMODEL - 1);
    int t = idx >> 10;
    float acc = 0.f;
#pragma unroll
    for (int j = 0; j < 4; j++) {
        int tt = t + j - 3;
        if (tt >= 0) acc += xin[tt * DMODEL + c] * w[c * 4 + j];
    }
    out[idx] = acc / (1.f + expf(-acc));
}

// ---------------- beta (sigmoid) + gate probs ------------------------------
__global__ void beta_gate_kernel(const float* __restrict__ x,
                                 const float* __restrict__ Wb,
                                 const float* __restrict__ gate_w,
                                 const float* __restrict__ gate_b,
                                 const float* __restrict__ log_temp,
                                 const float* __restrict__ eps_param,
                                 float* __restrict__ beta_out,
                                 float* __restrict__ probs_out) {
    int t = blockIdx.x;
    __shared__ float sx[DMODEL];
    __shared__ float sdot[24];
    int tid = threadIdx.x;
    for (int i = tid; i < DMODEL; i += 256) sx[i] = x[t * DMODEL + i];
    __syncthreads();
    int warp = tid >> 5, lane = tid & 31;
    for (int o = warp; o < 24; o += 8) {
        const float* wrow = (o < 4) ? (Wb + o * DMODEL) : (gate_w + (o - 4) * DMODEL);
        float s = 0.f;
        for (int i = lane; i < DMODEL; i += 32) s += sx[i] * wrow[i];
#pragma unroll
        for (int off = 16; off; off >>= 1) s += __shfl_xor_sync(0xffffffffu, s, off);
        if (lane == 0) sdot[o] = s;
    }
    __syncthreads();
    if (tid < NH) {
        int h = tid;
        beta_out[t * NH + h] = 1.f / (1.f + expf(-sdot[h]));
        float temp = expf(log_temp[h]);
        float lg[5], mx = -1e30f;
#pragma unroll
        for (int p = 0; p < 5; p++) {
            lg[p] = (sdot[4 + h * 5 + p] + gate_b[h * 5 + p]) / temp;
            mx = fmaxf(mx, lg[p]);
        }
        float se = 0.f;
#pragma unroll
        for (int p = 0; p < 5; p++) { lg[p] = expf(lg[p] - mx); se += lg[p]; }
        float eps = fminf(fmaxf(eps_param[h], 0.f), 0.2f);
#pragma unroll
        for (int p = 0; p < 5; p++)
            probs_out[(t * NH + h) * 5 + p] = lg[p] / se * (1.f - 5.f * eps) + eps;
    }
}

// ---------------- l2 norm of q,k over head dim (in place) ------------------
__global__ void l2norm_qk_kernel(float* __restrict__ q, float* __restrict__ k) {
    int row = blockIdx.x;
    int t = row >> 2, h = row & 3;
    int base = t * DMODEL + h * DHEAD;
    int d = threadIdx.x;
    float qv = q[base + d], kv = k[base + d];
    float sq = qv * qv, sk = kv * kv;
#pragma unroll
    for (int off = 16; off; off >>= 1) {
        sq += __shfl_xor_sync(0xffffffffu, sq, off);
        sk += __shfl_xor_sync(0xffffffffu, sk, off);
    }
    __shared__ float red[2][8];
    int warp = d >> 5, lane = d & 31;
    if (lane == 0) { red[0][warp] = sq; red[1][warp] = sk; }
    __syncthreads();
    float ssq = 0.f, ssk = 0.f;
#pragma unroll
    for (int i = 0; i < 8; i++) { ssq += red[0][i]; ssk += red[1][i]; }
    q[base + d] = qv * rsqrtf(ssq + 1e-6f);
    k[base + d] = kv * rsqrtf(ssk + 1e-6f);
}

// ---------------- per-chunk UT transform (parallel over chunks) ------------
#define CP_SMEM_FLOATS (2 * 32 * 257 + 2 * 32 * 33 + 32)
__global__ __launch_bounds__(256) void chunk_prep_kernel(const float* __restrict__ q,
                                                         const float* __restrict__ k,
                                                         const float* __restrict__ v,
                                                         const float* __restrict__ beta,
                                                         float* __restrict__ gu,
                                                         float* __restrict__ gw,
                                                         float* __restrict__ gattn) {
    extern __shared__ float smemf[];
    float (*sk)[257] = (float (*)[257])smemf;
    float (*sx)[257] = (float (*)[257])(smemf + 32 * 257);
    float (*sA)[33]  = (float (*)[33])(smemf + 2 * 32 * 257);
    float (*sT)[33]  = (float (*)[33])(smemf + 2 * 32 * 257 + 32 * 33);
    float* sbeta     = smemf + 2 * 32 * 257 + 2 * 32 * 33;

    int hb = blockIdx.x;
    int h = hb >> 6, ch = hb & 63;
    int t0 = ch * CSZ;
    int tid = threadIdx.x;

    for (int i = tid; i < CSZ * DHEAD; i += 256) {
        int r = i >> 8, d = i & 255;
        sk[r][d] = k[(t0 + r) * DMODEL + h * DHEAD + d];
    }
    if (tid < CSZ) sbeta[tid] = beta[(t0 + tid) * NH + h];
    __syncthreads();

    for (int p = tid; p < CSZ * CSZ; p += 256) {
        int i = p >> 5, j = p & 31;
        float a = 0.f;
        if (j < i) {
            float s = 0.f;
            for (int d = 0; d < DHEAD; d++) s += sk[i][d] * sk[j][d];
            a = -sbeta[i] * s;
        }
        sA[i][j] = a;
    }
    __syncthreads();

    if (tid < 32) {
        int col = tid;
        for (int i = 0; i < CSZ; i++) {
            float tv = (col == i) ? 1.f : 0.f;
            for (int j = 0; j < i; j++) tv += sA[i][j] * sT[j][col];
            sT[i][col] = tv;
            __syncwarp();
        }
    }
    __syncthreads();

    for (int i = tid; i < CSZ * DHEAD; i += 256) {
        int r = i >> 8, d = i & 255;
        sx[r][d] = v[(t0 + r) * DMODEL + h * DHEAD + d] * sbeta[r];
    }
    __syncthreads();
    {
        int d = tid;
        for (int i = 0; i < CSZ; i++) {
            float a = 0.f;
            for (int j = 0; j <= i; j++) a += sT[i][j] * sx[j][d];
            gu[(t0 + i) * DMODEL + h * DHEAD + d] = a;
        }
    }
    {
        int d = tid;
        for (int i = 0; i < CSZ; i++) {
            float a = 0.f;
            for (int j = 0; j <= i; j++) a += sT[i][j] * sbeta[j] * sk[j][d];
            gw[(t0 + i) * DMODEL + h * DHEAD + d] = a;
        }
    }
    __syncthreads();
    for (int i = tid; i < CSZ * DHEAD; i += 256) {
        int r = i >> 8, d = i & 255;
        sx[r][d] = q[(t0 + r) * DMODEL + h * DHEAD + d];
    }
    __syncthreads();
    for (int p = tid; p < CSZ * CSZ; p += 256) {
        int i = p >> 5, j = p & 31;
        float a = 0.f;
        if (j <= i) {
            float s = 0.f;
            for (int d = 0; d < DHEAD; d++) s += sx[i][d] * sk[j][d];
            a = s;
        }
        gattn[(hb * CSZ + i) * CSZ + j] = a;
    }
}

// ---------------- sequential chunk scan, parallel over (head, dv-slice) ----
#define SCAN_SMEM_FLOATS (3 * 32 * 256 + 256 * 9 + 256 + 256 + 1024)
__global__ __launch_bounds__(256) void delta_scan_kernel(const float* __restrict__ q,
                                                         const float* __restrict__ k,
                                                         const float* __restrict__ w,
                                                         const float* __restrict__ u,
                                                         const float* __restrict__ attn,
                                                         float* __restrict__ dout) {
    extern __shared__ float smemf[];
    float (*sq)[256]  = (float (*)[256])smemf;
    float (*skk)[256] = (float (*)[256])(smemf + 8192);
    float (*sw)[256]  = (float (*)[256])(smemf + 16384);
    float (*S)[9]     = (float (*)[9])(smemf + 24576);
    float* su   = smemf + 24576 + 2304;
    float* sua  = su + 256;
    float* satt = sua + 256;

    int b = blockIdx.x;
    int h = b >> 5, sl = b & 31;
    int tid = threadIdx.x;
    int r = tid >> 3, c = tid & 7;
    int cbase = h * DHEAD + sl * 8;

    float Sreg[8];
#pragma unroll
    for (int i = 0; i < 8; i++) Sreg[i] = 0.f;

    for (int ch = 0; ch < NCHUNK; ch++) {
        int t0 = ch * CSZ;
#pragma unroll
        for (int i = 0; i < 8; i++) S[tid][i] = Sreg[i];
        for (int i = tid; i < CSZ * DHEAD; i += 256) {
            int rr = i >> 8, d = i & 255;
            int gidx = (t0 + rr) * DMODEL + h * DHEAD + d;
            sq[rr][d]  = q[gidx];
            skk[rr][d] = k[gidx];
            sw[rr][d]  = w[gidx];
        }
        su[tid] = u[(t0 + r) * DMODEL + cbase + c];
        for (int i = tid; i < CSZ * CSZ; i += 256)
            satt[i] = attn[(h * NCHUNK + ch) * CSZ * CSZ + i];
        __syncthreads();

        float au = su[tid], ao = 0.f;
#pragma unroll 8
        for (int d = 0; d < DHEAD; d++) {
            float sval = S[d][c];
            au = fmaf(-sw[r][d], sval, au);
            ao = fmaf(sq[r][d], sval, ao);
        }
        sua[tid] = au;
        __syncthreads();
#pragma unroll
        for (int j = 0; j < CSZ; j++) ao = fmaf(satt[r * CSZ + j], sua[j * 8 + c], ao);
        dout[(t0 + r) * DMODEL + cbase + c] = ao;

#pragma unroll 8
        for (int j = 0; j < CSZ; j++) {
            float kv = skk[j][tid];
#pragma unroll
            for (int cc = 0; cc < 8; cc++) Sreg[cc] = fmaf(kv, sua[j * 8 + cc], Sreg[cc]);
        }
        __syncthreads();
    }
}

// ---------------- FIR(3/15/63) + gated mix + per-head RMSNorm --------------
__global__ void combine_kernel(const float* __restrict__ v,
                               const float* __restrict__ delta,
                               const float* __restrict__ probs,
                               const float* __restrict__ fs,
                               const float* __restrict__ fm,
                               const float* __restrict__ fl,
                               const float* __restrict__ normw,
                               float* __restrict__ out) {
    int row = blockIdx.x;
    int t = row >> 2, h = row & 3;
    int d = threadIdx.x;
    int cidx = h * DHEAD + d;
    const float* pb = probs + (t * NH + h) * 5;
    float p0 = pb[0], p1 = pb[1], p2 = pb[2], p3 = pb[3], p4 = pb[4];

    float ll = 0.f;
    for (int kk = 0; kk < 63; kk++) {
        int tt = t + kk - 62;
        if (tt >= 0) ll = fmaf(v[tt * DMODEL + cidx], fl[cidx * 63 + kk], ll);
    }
    float lm = 0.f;
#pragma unroll
    for (int kk = 0; kk < 15; kk++) {
        int tt = t + kk - 14;
        if (tt >= 0) lm = fmaf(v[tt * DMODEL + cidx], fm[cidx * 15 + kk], lm);
    }
    float ls = 0.f;
#pragma unroll
    for (int kk = 0; kk < 3; kk++) {
        int tt = t + kk - 2;
        if (tt >= 0) ls = fmaf(v[tt * DMODEL + cidx], fs[cidx * 3 + kk], ls);
    }
    float vcur = v[t * DMODEL + cidx];
    float mix = p0 * ls + p1 * lm + p2 * ll + p3 * delta[t * DMODEL + cidx] + p4 * vcur;

    float s = mix * mix;
#pragma unroll
    for (int off = 16; off; off >>= 1) s += __shfl_xor_sync(0xffffffffu, s, off);
    __shared__ float red[8];
    int warp = d >> 5, lane = d & 31;
    if (lane == 0) red[warp] = s;
    __syncthreads();
    float ms = 0.f;
#pragma unroll
    for (int i = 0; i < 8; i++) ms += red[i];
    out[t * DMODEL + cidx] = mix * rsqrtf(ms * (1.f / 256.f) + 1e-5f) * normw[d];
}

// ---------------- launch ---------------------------------------------------
extern "C" void kernel_launch(void* const* d_in, const int* in_sizes, int n_in,
                              void* d_out, int out_size) {
    const float* x       = (const float*)d_in[0];
    const float* Wq      = (const float*)d_in[1];
    const float* Wk      = (const float*)d_in[2];
    const float* Wv      = (const float*)d_in[3];
    const float* Wb      = (const float*)d_in[4];
    const float* conv_q  = (const float*)d_in[5];
    const float* conv_k  = (const float*)d_in[6];
    const float* conv_v  = (const float*)d_in[7];
    const float* fir_s   = (const float*)d_in[8];
    const float* fir_m   = (const float*)d_in[9];
    const float* fir_l   = (const float*)d_in[10];
    const float* gate_w  = (const float*)d_in[11];
    const float* gate_b  = (const float*)d_in[12];
    const float* log_tmp = (const float*)d_in[13];
    const float* eps_p   = (const float*)d_in[14];
    const float* norm_w  = (const float*)d_in[15];
    const float* Wo      = (const float*)d_in[16];
    float* out = (float*)d_out;

    float *qlin, *klin, *vlin, *qb, *kb, *vb, *ub, *wb, *db, *mixb, *betab, *probsb, *attnb;
    cudaGetSymbolAddress((void**)&qlin,  g_qlin);
    cudaGetSymbolAddress((void**)&klin,  g_klin);
    cudaGetSymbolAddress((void**)&vlin,  g_vlin);
    cudaGetSymbolAddress((void**)&qb,    g_q);
    cudaGetSymbolAddress((void**)&kb,    g_k);
    cudaGetSymbolAddress((void**)&vb,    g_v);
    cudaGetSymbolAddress((void**)&ub,    g_u);
    cudaGetSymbolAddress((void**)&wb,    g_w);
    cudaGetSymbolAddress((void**)&db,    g_delta);
    cudaGetSymbolAddress((void**)&mixb,  g_mix);
    cudaGetSymbolAddress((void**)&betab, g_beta);
    cudaGetSymbolAddress((void**)&probsb, g_probs);
    cudaGetSymbolAddress((void**)&attnb, g_attn);

    __nv_bfloat16 *xhi, *xlo, *wqhi, *wqlo, *wkhi, *wklo, *wvhi, *wvlo, *wohi, *wolo,
                  *mixhi, *mixlo;
    cudaGetSymbolAddress((void**)&xhi, g_xhi);   cudaGetSymbolAddress((void**)&xlo, g_xlo);
    cudaGetSymbolAddress((void**)&wqhi, g_wqhi); cudaGetSymbolAddress((void**)&wqlo, g_wqlo);
    cudaGetSymbolAddress((void**)&wkhi, g_wkhi); cudaGetSymbolAddress((void**)&wklo, g_wklo);
    cudaGetSymbolAddress((void**)&wvhi, g_wvhi); cudaGetSymbolAddress((void**)&wvlo, g_wvlo);
    cudaGetSymbolAddress((void**)&wohi, g_wohi); cudaGetSymbolAddress((void**)&wolo, g_wolo);
    cudaGetSymbolAddress((void**)&mixhi, g_mixhi); cudaGetSymbolAddress((void**)&mixlo, g_mixlo);

    cudaFuncSetAttribute(hgemm_nt, cudaFuncAttributeMaxDynamicSharedMemorySize, HG_SMEM);
    cudaFuncSetAttribute(chunk_prep_kernel, cudaFuncAttributeMaxDynamicSharedMemorySize,
                         CP_SMEM_FLOATS * 4);
    cudaFuncSetAttribute(delta_scan_kernel, cudaFuncAttributeMaxDynamicSharedMemorySize,
                         SCAN_SMEM_FLOATS * 4);

    int nX4 = SEQ * DMODEL / 4;
    int nW4 = DMODEL * DMODEL / 4;
    split_kernel<<<(nX4 + 255) / 256, 256>>>(x, xhi, xlo, nX4);      // launch 0
    split_kernel<<<(nW4 + 255) / 256, 256>>>(Wq, wqhi, wqlo, nW4);   // 1
    split_kernel<<<(nW4 + 255) / 256, 256>>>(Wk, wkhi, wklo, nW4);   // 2
    split_kernel<<<(nW4 + 255) / 256, 256>>>(Wv, wvhi, wvlo, nW4);   // 3
    split_kernel<<<(nW4 + 255) / 256, 256>>>(Wo, wohi, wolo, nW4);   // 4

    dim3 tg(DMODEL / 128, SEQ / 128);  // (8, 16)
    hgemm_nt<<<tg, 256, HG_SMEM>>>(xhi, xlo, wqhi, wqlo, qlin, SEQ, DMODEL, DMODEL); // 5 (ncu)
    hgemm_nt<<<tg, 256, HG_SMEM>>>(xhi, xlo, wkhi, wklo, klin, SEQ, DMODEL, DMODEL);
    hgemm_nt<<<tg, 256, HG_SMEM>>>(xhi, xlo, wvhi, wvlo, vlin, SEQ, DMODEL, DMODEL);

    int nelem = SEQ * DMODEL;
    conv_silu_kernel<<<nelem / 256, 256>>>(qlin, conv_q, qb);
    conv_silu_kernel<<<nelem / 256, 256>>>(klin, conv_k, kb);
    conv_silu_kernel<<<nelem / 256, 256>>>(vlin, conv_v, vb);

    beta_gate_kernel<<<SEQ, 256>>>(x, Wb, gate_w, gate_b, log_tmp, eps_p, betab, probsb);
    l2norm_qk_kernel<<<SEQ * NH, 256>>>(qb, kb);

    chunk_prep_kernel<<<NH * NCHUNK, 256, CP_SMEM_FLOATS * 4>>>(qb, kb, vb, betab,
                                                                ub, wb, attnb);
    delta_scan_kernel<<<NH * 32, 256, SCAN_SMEM_FLOATS * 4>>>(qb, kb, wb, ub, attnb, db);

    combine_kernel<<<SEQ * NH, 256>>>(vb, db, probsb, fir_s, fir_m, fir_l, norm_w, mixb);

    split_kernel<<<(nX4 + 255) / 256, 256>>>(mixb, mixhi, mixlo, nX4);
    hgemm_nt<<<tg, 256, HG_SMEM>>>(mixhi, mixlo, wohi, wolo, out, SEQ, DMODEL, DMODEL);
}

// round 6
// speedup vs baseline: 1.0691x; 1.0691x over previous
#include <cuda_runtime.h>
#include <cuda_bf16.h>
#include <cstdint>
#include <math.h>

// Problem constants
#define SEQ    2048
#define DMODEL 1024
#define NH     4
#define DHEAD  256
#define NCHUNK 64
#define CSZ    32

// ---------------- scratch (device globals; allocation-free) ----------------
__device__ __align__(16) float g_qlin[SEQ * DMODEL];
__device__ __align__(16) float g_klin[SEQ * DMODEL];
__device__ __align__(16) float g_vlin[SEQ * DMODEL];
__device__ __align__(16) float g_q[SEQ * DMODEL];
__device__ __align__(16) float g_k[SEQ * DMODEL];
__device__ __align__(16) float g_v[SEQ * DMODEL];
__device__ __align__(16) float g_u[SEQ * DMODEL];
__device__ __align__(16) float g_w[SEQ * DMODEL];
__device__ __align__(16) float g_delta[SEQ * DMODEL];
__device__ __align__(16) float g_mix[SEQ * DMODEL];
__device__ __align__(16) float g_beta[SEQ * NH];
__device__ __align__(16) float g_probs[SEQ * NH * 5];
__device__ __align__(16) float g_attn[NH * NCHUNK * CSZ * CSZ];

// bf16 hi/lo split buffers
__device__ __align__(16) __nv_bfloat16 g_xhi[SEQ * DMODEL];
__device__ __align__(16) __nv_bfloat16 g_xlo[SEQ * DMODEL];
__device__ __align__(16) __nv_bfloat16 g_wqhi[DMODEL * DMODEL];
__device__ __align__(16) __nv_bfloat16 g_wqlo[DMODEL * DMODEL];
__device__ __align__(16) __nv_bfloat16 g_wkhi[DMODEL * DMODEL];
__device__ __align__(16) __nv_bfloat16 g_wklo[DMODEL * DMODEL];
__device__ __align__(16) __nv_bfloat16 g_wvhi[DMODEL * DMODEL];
__device__ __align__(16) __nv_bfloat16 g_wvlo[DMODEL * DMODEL];
__device__ __align__(16) __nv_bfloat16 g_wohi[DMODEL * DMODEL];
__device__ __align__(16) __nv_bfloat16 g_wolo[DMODEL * DMODEL];
__device__ __align__(16) __nv_bfloat16 g_mixhi[SEQ * DMODEL];
__device__ __align__(16) __nv_bfloat16 g_mixlo[SEQ * DMODEL];

// ---------------- bf16 hi/lo tensor-core GEMM v2: C = A * B^T ---------------
// Tile 128(M) x 64(N), K-chunk 32, cp.async double-buffer, grid 256 CTAs.
// smem row stride 80B (conflict-free for fragment LDS pattern).
#define HG_STRIDE 80
#define HG_AT     (128 * HG_STRIDE)          // 10240 per A tile
#define HG_BT     (64 * HG_STRIDE)           // 5120  per B tile
#define HG_BUFB   (2 * HG_AT + 2 * HG_BT)    // 30720: AH, AL, BH, BL
#define HG_SMEM   (2 * HG_BUFB)              // 61440

__device__ __forceinline__ void mma_bf16(float* acc, const unsigned* a,
                                         const unsigned* b) {
    asm volatile(
        "mma.sync.aligned.m16n8k16.row.col.f32.bf16.bf16.f32 "
        "{%0,%1,%2,%3}, {%4,%5,%6,%7}, {%8,%9}, {%0,%1,%2,%3};"
        : "+f"(acc[0]), "+f"(acc[1]), "+f"(acc[2]), "+f"(acc[3])
        : "r"(a[0]), "r"(a[1]), "r"(a[2]), "r"(a[3]), "r"(b[0]), "r"(b[1]));
}
__device__ __forceinline__ void cp16(unsigned saddr, const void* g) {
    asm volatile("cp.async.cg.shared.global [%0], [%1], 16;"
                 :: "r"(saddr), "l"(g) : "memory");
}

__global__ __launch_bounds__(256, 2) void hgemm_nt(const __nv_bfloat16* __restrict__ Ahi,
                                                   const __nv_bfloat16* __restrict__ Alo,
                                                   const __nv_bfloat16* __restrict__ Bhi,
                                                   const __nv_bfloat16* __restrict__ Blo,
                                                   float* __restrict__ C,
                                                   int M, int N, int K) {
    extern __shared__ __align__(16) char smem[];
    unsigned sbase;
    asm("{ .reg .u64 t; cvta.to.shared.u64 t, %1; cvt.u32.u64 %0, t; }"
        : "=r"(sbase) : "l"(smem));
    int tid = threadIdx.x;
    int warp = tid >> 5, lane = tid & 31;
    int wm = warp >> 2;          // 0..1 -> M offset 64
    int wn = warp & 3;           // 0..3 -> N offset 16
    int g = lane >> 2, t = lane & 3;
    int bm = blockIdx.y * 128, bn = blockIdx.x * 64;

    float acc[4][2][4];
#pragma unroll
    for (int mi = 0; mi < 4; mi++)
#pragma unroll
        for (int nj = 0; nj < 2; nj++)
#pragma unroll
            for (int r = 0; r < 4; r++) acc[mi][nj][r] = 0.f;

    // cp.async issue for one chunk (6 x 16B per thread)
#define HG_ISSUE(k0, buf)                                                           \
    do {                                                                            \
        unsigned bb = sbase + (buf) * HG_BUFB;                                      \
        _Pragma("unroll")                                                           \
        for (int it = 0; it < 2; it++) {                                            \
            int idx = tid + it * 256;                                               \
            int row = idx >> 2, quad = idx & 3;                                     \
            unsigned so = bb + row * HG_STRIDE + quad * 16;                         \
            size_t ga = (size_t)(bm + row) * K + (k0) + quad * 8;                   \
            cp16(so, Ahi + ga);                                                     \
            cp16(so + HG_AT, Alo + ga);                                             \
        }                                                                           \
        {                                                                           \
            int row = tid >> 2, quad = tid & 3;                                     \
            unsigned so = bb + 2 * HG_AT + row * HG_STRIDE + quad * 16;             \
            size_t gb = (size_t)(bn + row) * K + (k0) + quad * 8;                   \
            cp16(so, Bhi + gb);                                                     \
            cp16(so + HG_BT, Blo + gb);                                             \
        }                                                                           \
        asm volatile("cp.async.commit_group;" ::: "memory");                        \
    } while (0)

    HG_ISSUE(0, 0);

    const int nch = K / 32;
    int buf = 0;
    for (int ch = 0; ch < nch; ch++) {
        if (ch + 1 < nch) {
            HG_ISSUE((ch + 1) * 32, buf ^ 1);
            asm volatile("cp.async.wait_group 1;" ::: "memory");
        } else {
            asm volatile("cp.async.wait_group 0;" ::: "memory");
        }
        __syncthreads();

        const char* AH = smem + buf * HG_BUFB;
        const char* AL = AH + HG_AT;
        const char* BH = AH + 2 * HG_AT;
        const char* BL = BH + HG_BT;

#pragma unroll
        for (int ks = 0; ks < 2; ks++) {
            int kb = ks * 32;   // byte offset within row (16 bf16)
            unsigned ah[4][4], al[4][4], bh[2][2], bl[2][2];
#pragma unroll
            for (int mi = 0; mi < 4; mi++) {
                int r0 = wm * 64 + mi * 16 + g;
                ah[mi][0] = *(const unsigned*)(AH + r0 * HG_STRIDE + kb + t * 4);
                ah[mi][1] = *(const unsigned*)(AH + (r0 + 8) * HG_STRIDE + kb + t * 4);
                ah[mi][2] = *(const unsigned*)(AH + r0 * HG_STRIDE + kb + 16 + t * 4);
                ah[mi][3] = *(const unsigned*)(AH + (r0 + 8) * HG_STRIDE + kb + 16 + t * 4);
                al[mi][0] = *(const unsigned*)(AL + r0 * HG_STRIDE + kb + t * 4);
                al[mi][1] = *(const unsigned*)(AL + (r0 + 8) * HG_STRIDE + kb + t * 4);
                al[mi][2] = *(const unsigned*)(AL + r0 * HG_STRIDE + kb + 16 + t * 4);
                al[mi][3] = *(const unsigned*)(AL + (r0 + 8) * HG_STRIDE + kb + 16 + t * 4);
            }
#pragma unroll
            for (int nj = 0; nj < 2; nj++) {
                int n = wn * 16 + nj * 8 + g;
                bh[nj][0] = *(const unsigned*)(BH + n * HG_STRIDE + kb + t * 4);
                bh[nj][1] = *(const unsigned*)(BH + n * HG_STRIDE + kb + 16 + t * 4);
                bl[nj][0] = *(const unsigned*)(BL + n * HG_STRIDE + kb + t * 4);
                bl[nj][1] = *(const unsigned*)(BL + n * HG_STRIDE + kb + 16 + t * 4);
            }
#pragma unroll
            for (int mi = 0; mi < 4; mi++)
#pragma unroll
                for (int nj = 0; nj < 2; nj++) {
                    mma_bf16(acc[mi][nj], ah[mi], bh[nj]);
                    mma_bf16(acc[mi][nj], ah[mi], bl[nj]);
                    mma_bf16(acc[mi][nj], al[mi], bh[nj]);
                }
        }
        __syncthreads();
        buf ^= 1;
    }

#pragma unroll
    for (int mi = 0; mi < 4; mi++) {
        int row = bm + wm * 64 + mi * 16 + g;
#pragma unroll
        for (int nj = 0; nj < 2; nj++) {
            int col = bn + wn * 16 + nj * 8 + t * 2;
            *(float2*)(C + (size_t)row * N + col) =
                make_float2(acc[mi][nj][0], acc[mi][nj][1]);
            *(float2*)(C + (size_t)(row + 8) * N + col) =
                make_float2(acc[mi][nj][2], acc[mi][nj][3]);
        }
    }
#undef HG_ISSUE
}

// ---------------- fp32 -> bf16 hi/lo split ---------------------------------
__global__ void split_kernel(const float* __restrict__ in,
                             __nv_bfloat16* __restrict__ hi,
                             __nv_bfloat16* __restrict__ lo, int n4) {
    int i = blockIdx.x * 256 + threadIdx.x;
    if (i >= n4) return;
    float4 v = ((const float4*)in)[i];
    float vv[4] = {v.x, v.y, v.z, v.w};
    __align__(8) __nv_bfloat16 h[4];
    __align__(8) __nv_bfloat16 l[4];
#pragma unroll
    for (int j = 0; j < 4; j++) {
        h[j] = __float2bfloat16(vv[j]);
        l[j] = __float2bfloat16(vv[j] - __bfloat162float(h[j]));
    }
    ((uint2*)hi)[i] = *(uint2*)h;
    ((uint2*)lo)[i] = *(uint2*)l;
}

// ---------------- short conv (K=4, causal) + silu --------------------------
__global__ void conv_silu_kernel(const float* __restrict__ xin,
                                 const float* __restrict__ w,
                                 float* __restrict__ out) {
    int idx = blockIdx.x * blockDim.x + threadIdx.x;
    int c = idx & (DMODEL - 1);
    int t = idx >> 10;
    float acc = 0.f;
#pragma unroll
    for (int j = 0; j < 4; j++) {
        int tt = t + j - 3;
        if (tt >= 0) acc += xin[tt * DMODEL + c] * w[c * 4 + j];
    }
    out[idx] = acc / (1.f + expf(-acc));
}

// ---------------- beta (sigmoid) + gate probs ------------------------------
__global__ void beta_gate_kernel(const float* __restrict__ x,
                                 const float* __restrict__ Wb,
                                 const float* __restrict__ gate_w,
                                 const float* __restrict__ gate_b,
                                 const float* __restrict__ log_temp,
                                 const float* __restrict__ eps_param,
                                 float* __restrict__ beta_out,
                                 float* __restrict__ probs_out) {
    int t = blockIdx.x;
    __shared__ float sx[DMODEL];
    __shared__ float sdot[24];
    int tid = threadIdx.x;
    for (int i = tid; i < DMODEL; i += 256) sx[i] = x[t * DMODEL + i];
    __syncthreads();
    int warp = tid >> 5, lane = tid & 31;
    for (int o = warp; o < 24; o += 8) {
        const float* wrow = (o < 4) ? (Wb + o * DMODEL) : (gate_w + (o - 4) * DMODEL);
        float s = 0.f;
        for (int i = lane; i < DMODEL; i += 32) s += sx[i] * wrow[i];
#pragma unroll
        for (int off = 16; off; off >>= 1) s += __shfl_xor_sync(0xffffffffu, s, off);
        if (lane == 0) sdot[o] = s;
    }
    __syncthreads();
    if (tid < NH) {
        int h = tid;
        beta_out[t * NH + h] = 1.f / (1.f + expf(-sdot[h]));
        float temp = expf(log_temp[h]);
        float lg[5], mx = -1e30f;
#pragma unroll
        for (int p = 0; p < 5; p++) {
            lg[p] = (sdot[4 + h * 5 + p] + gate_b[h * 5 + p]) / temp;
            mx = fmaxf(mx, lg[p]);
        }
        float se = 0.f;
#pragma unroll
        for (int p = 0; p < 5; p++) { lg[p] = expf(lg[p] - mx); se += lg[p]; }
        float eps = fminf(fmaxf(eps_param[h], 0.f), 0.2f);
#pragma unroll
        for (int p = 0; p < 5; p++)
            probs_out[(t * NH + h) * 5 + p] = lg[p] / se * (1.f - 5.f * eps) + eps;
    }
}

// ---------------- l2 norm of q,k over head dim (in place) ------------------
__global__ void l2norm_qk_kernel(float* __restrict__ q, float* __restrict__ k) {
    int row = blockIdx.x;
    int t = row >> 2, h = row & 3;
    int base = t * DMODEL + h * DHEAD;
    int d = threadIdx.x;
    float qv = q[base + d], kv = k[base + d];
    float sq = qv * qv, sk = kv * kv;
#pragma unroll
    for (int off = 16; off; off >>= 1) {
        sq += __shfl_xor_sync(0xffffffffu, sq, off);
        sk += __shfl_xor_sync(0xffffffffu, sk, off);
    }
    __shared__ float red[2][8];
    int warp = d >> 5, lane = d & 31;
    if (lane == 0) { red[0][warp] = sq; red[1][warp] = sk; }
    __syncthreads();
    float ssq = 0.f, ssk = 0.f;
#pragma unroll
    for (int i = 0; i < 8; i++) { ssq += red[0][i]; ssk += red[1][i]; }
    q[base + d] = qv * rsqrtf(ssq + 1e-6f);
    k[base + d] = kv * rsqrtf(ssk + 1e-6f);
}

// ---------------- per-chunk UT transform (parallel over chunks) ------------
#define CP_SMEM_FLOATS (2 * 32 * 257 + 2 * 32 * 33 + 32)
__global__ __launch_bounds__(256) void chunk_prep_kernel(const float* __restrict__ q,
                                                         const float* __restrict__ k,
                                                         const float* __restrict__ v,
                                                         const float* __restrict__ beta,
                                                         float* __restrict__ gu,
                                                         float* __restrict__ gw,
                                                         float* __restrict__ gattn) {
    extern __shared__ float smemf[];
    float (*sk)[257] = (float (*)[257])smemf;
    float (*sx)[257] = (float (*)[257])(smemf + 32 * 257);
    float (*sA)[33]  = (float (*)[33])(smemf + 2 * 32 * 257);
    float (*sT)[33]  = (float (*)[33])(smemf + 2 * 32 * 257 + 32 * 33);
    float* sbeta     = smemf + 2 * 32 * 257 + 2 * 32 * 33;

    int hb = blockIdx.x;
    int h = hb >> 6, ch = hb & 63;
    int t0 = ch * CSZ;
    int tid = threadIdx.x;

    for (int i = tid; i < CSZ * DHEAD; i += 256) {
        int r = i >> 8, d = i & 255;
        sk[r][d] = k[(t0 + r) * DMODEL + h * DHEAD + d];
    }
    if (tid < CSZ) sbeta[tid] = beta[(t0 + tid) * NH + h];
    __syncthreads();

    for (int p = tid; p < CSZ * CSZ; p += 256) {
        int i = p >> 5, j = p & 31;
        float a = 0.f;
        if (j < i) {
            float s = 0.f;
            for (int d = 0; d < DHEAD; d++) s += sk[i][d] * sk[j][d];
            a = -sbeta[i] * s;
        }
        sA[i][j] = a;
    }
    __syncthreads();

    if (tid < 32) {
        int col = tid;
        for (int i = 0; i < CSZ; i++) {
            float tv = (col == i) ? 1.f : 0.f;
            for (int j = 0; j < i; j++) tv += sA[i][j] * sT[j][col];
            sT[i][col] = tv;
            __syncwarp();
        }
    }
    __syncthreads();

    for (int i = tid; i < CSZ * DHEAD; i += 256) {
        int r = i >> 8, d = i & 255;
        sx[r][d] = v[(t0 + r) * DMODEL + h * DHEAD + d] * sbeta[r];
    }
    __syncthreads();
    {
        int d = tid;
        for (int i = 0; i < CSZ; i++) {
            float a = 0.f;
            for (int j = 0; j <= i; j++) a += sT[i][j] * sx[j][d];
            gu[(t0 + i) * DMODEL + h * DHEAD + d] = a;
        }
    }
    {
        int d = tid;
        for (int i = 0; i < CSZ; i++) {
            float a = 0.f;
            for (int j = 0; j <= i; j++) a += sT[i][j] * sbeta[j] * sk[j][d];
            gw[(t0 + i) * DMODEL + h * DHEAD + d] = a;
        }
    }
    __syncthreads();
    for (int i = tid; i < CSZ * DHEAD; i += 256) {
        int r = i >> 8, d = i & 255;
        sx[r][d] = q[(t0 + r) * DMODEL + h * DHEAD + d];
    }
    __syncthreads();
    for (int p = tid; p < CSZ * CSZ; p += 256) {
        int i = p >> 5, j = p & 31;
        float a = 0.f;
        if (j <= i) {
            float s = 0.f;
            for (int d = 0; d < DHEAD; d++) s += sx[i][d] * sk[j][d];
            a = s;
        }
        gattn[(hb * CSZ + i) * CSZ + j] = a;
    }
}

// ---------------- sequential chunk scan, parallel over (head, dv-slice) ----
#define SCAN_SMEM_FLOATS (3 * 32 * 256 + 256 * 9 + 256 + 256 + 1024)
__global__ __launch_bounds__(256) void delta_scan_kernel(const float* __restrict__ q,
                                                         const float* __restrict__ k,
                                                         const float* __restrict__ w,
                                                         const float* __restrict__ u,
                                                         const float* __restrict__ attn,
                                                         float* __restrict__ dout) {
    extern __shared__ float smemf[];
    float (*sq)[256]  = (float (*)[256])smemf;
    float (*skk)[256] = (float (*)[256])(smemf + 8192);
    float (*sw)[256]  = (float (*)[256])(smemf + 16384);
    float (*S)[9]     = (float (*)[9])(smemf + 24576);
    float* su   = smemf + 24576 + 2304;
    float* sua  = su + 256;
    float* satt = sua + 256;

    int b = blockIdx.x;
    int h = b >> 5, sl = b & 31;
    int tid = threadIdx.x;
    int r = tid >> 3, c = tid & 7;
    int cbase = h * DHEAD + sl * 8;

    float Sreg[8];
#pragma unroll
    for (int i = 0; i < 8; i++) Sreg[i] = 0.f;

    for (int ch = 0; ch < NCHUNK; ch++) {
        int t0 = ch * CSZ;
#pragma unroll
        for (int i = 0; i < 8; i++) S[tid][i] = Sreg[i];
        for (int i = tid; i < CSZ * DHEAD; i += 256) {
            int rr = i >> 8, d = i & 255;
            int gidx = (t0 + rr) * DMODEL + h * DHEAD + d;
            sq[rr][d]  = q[gidx];
            skk[rr][d] = k[gidx];
            sw[rr][d]  = w[gidx];
        }
        su[tid] = u[(t0 + r) * DMODEL + cbase + c];
        for (int i = tid; i < CSZ * CSZ; i += 256)
            satt[i] = attn[(h * NCHUNK + ch) * CSZ * CSZ + i];
        __syncthreads();

        float au = su[tid], ao = 0.f;
#pragma unroll 8
        for (int d = 0; d < DHEAD; d++) {
            float sval = S[d][c];
            au = fmaf(-sw[r][d], sval, au);
            ao = fmaf(sq[r][d], sval, ao);
        }
        sua[tid] = au;
        __syncthreads();
#pragma unroll
        for (int j = 0; j < CSZ; j++) ao = fmaf(satt[r * CSZ + j], sua[j * 8 + c], ao);
        dout[(t0 + r) * DMODEL + cbase + c] = ao;

#pragma unroll 8
        for (int j = 0; j < CSZ; j++) {
            float kv = skk[j][tid];
#pragma unroll
            for (int cc = 0; cc < 8; cc++) Sreg[cc] = fmaf(kv, sua[j * 8 + cc], Sreg[cc]);
        }
        __syncthreads();
    }
}

// ---------------- FIR(3/15/63) + gated mix + per-head RMSNorm --------------
__global__ void combine_kernel(const float* __restrict__ v,
                               const float* __restrict__ delta,
                               const float* __restrict__ probs,
                               const float* __restrict__ fs,
                               const float* __restrict__ fm,
                               const float* __restrict__ fl,
                               const float* __restrict__ normw,
                               float* __restrict__ out) {
    int row = blockIdx.x;
    int t = row >> 2, h = row & 3;
    int d = threadIdx.x;
    int cidx = h * DHEAD + d;
    const float* pb = probs + (t * NH + h) * 5;
    float p0 = pb[0], p1 = pb[1], p2 = pb[2], p3 = pb[3], p4 = pb[4];

    float ll = 0.f;
    for (int kk = 0; kk < 63; kk++) {
        int tt = t + kk - 62;
        if (tt >= 0) ll = fmaf(v[tt * DMODEL + cidx], fl[cidx * 63 + kk], ll);
    }
    float lm = 0.f;
#pragma unroll
    for (int kk = 0; kk < 15; kk++) {
        int tt = t + kk - 14;
        if (tt >= 0) lm = fmaf(v[tt * DMODEL + cidx], fm[cidx * 15 + kk], lm);
    }
    float ls = 0.f;
#pragma unroll
    for (int kk = 0; kk < 3; kk++) {
        int tt = t + kk - 2;
        if (tt >= 0) ls = fmaf(v[tt * DMODEL + cidx], fs[cidx * 3 + kk], ls);
    }
    float vcur = v[t * DMODEL + cidx];
    float mix = p0 * ls + p1 * lm + p2 * ll + p3 * delta[t * DMODEL + cidx] + p4 * vcur;

    float s = mix * mix;
#pragma unroll
    for (int off = 16; off; off >>= 1) s += __shfl_xor_sync(0xffffffffu, s, off);
    __shared__ float red[8];
    int warp = d >> 5, lane = d & 31;
    if (lane == 0) red[warp] = s;
    __syncthreads();
    float ms = 0.f;
#pragma unroll
    for (int i = 0; i < 8; i++) ms += red[i];
    out[t * DMODEL + cidx] = mix * rsqrtf(ms * (1.f / 256.f) + 1e-5f) * normw[d];
}

// ---------------- launch ---------------------------------------------------
extern "C" void kernel_launch(void* const* d_in, const int* in_sizes, int n_in,
                              void* d_out, int out_size) {
    const float* x       = (const float*)d_in[0];
    const float* Wq      = (const float*)d_in[1];
    const float* Wk      = (const float*)d_in[2];
    const float* Wv      = (const float*)d_in[3];
    const float* Wb      = (const float*)d_in[4];
    const float* conv_q  = (const float*)d_in[5];
    const float* conv_k  = (const float*)d_in[6];
    const float* conv_v  = (const float*)d_in[7];
    const float* fir_s   = (const float*)d_in[8];
    const float* fir_m   = (const float*)d_in[9];
    const float* fir_l   = (const float*)d_in[10];
    const float* gate_w  = (const float*)d_in[11];
    const float* gate_b  = (const float*)d_in[12];
    const float* log_tmp = (const float*)d_in[13];
    const float* eps_p   = (const float*)d_in[14];
    const float* norm_w  = (const float*)d_in[15];
    const float* Wo      = (const float*)d_in[16];
    float* out = (float*)d_out;

    float *qlin, *klin, *vlin, *qb, *kb, *vb, *ub, *wb, *db, *mixb, *betab, *probsb, *attnb;
    cudaGetSymbolAddress((void**)&qlin,  g_qlin);
    cudaGetSymbolAddress((void**)&klin,  g_klin);
    cudaGetSymbolAddress((void**)&vlin,  g_vlin);
    cudaGetSymbolAddress((void**)&qb,    g_q);
    cudaGetSymbolAddress((void**)&kb,    g_k);
    cudaGetSymbolAddress((void**)&vb,    g_v);
    cudaGetSymbolAddress((void**)&ub,    g_u);
    cudaGetSymbolAddress((void**)&wb,    g_w);
    cudaGetSymbolAddress((void**)&db,    g_delta);
    cudaGetSymbolAddress((void**)&mixb,  g_mix);
    cudaGetSymbolAddress((void**)&betab, g_beta);
    cudaGetSymbolAddress((void**)&probsb, g_probs);
    cudaGetSymbolAddress((void**)&attnb, g_attn);

    __nv_bfloat16 *xhi, *xlo, *wqhi, *wqlo, *wkhi, *wklo, *wvhi, *wvlo, *wohi, *wolo,
                  *mixhi, *mixlo;
    cudaGetSymbolAddress((void**)&xhi, g_xhi);   cudaGetSymbolAddress((void**)&xlo, g_xlo);
    cudaGetSymbolAddress((void**)&wqhi, g_wqhi); cudaGetSymbolAddress((void**)&wqlo, g_wqlo);
    cudaGetSymbolAddress((void**)&wkhi, g_wkhi); cudaGetSymbolAddress((void**)&wklo, g_wklo);
    cudaGetSymbolAddress((void**)&wvhi, g_wvhi); cudaGetSymbolAddress((void**)&wvlo, g_wvlo);
    cudaGetSymbolAddress((void**)&wohi, g_wohi); cudaGetSymbolAddress((void**)&wolo, g_wolo);
    cudaGetSymbolAddress((void**)&mixhi, g_mixhi); cudaGetSymbolAddress((void**)&mixlo, g_mixlo);

    cudaFuncSetAttribute(hgemm_nt, cudaFuncAttributeMaxDynamicSharedMemorySize, HG_SMEM);
    cudaFuncSetAttribute(chunk_prep_kernel, cudaFuncAttributeMaxDynamicSharedMemorySize,
                         CP_SMEM_FLOATS * 4);
    cudaFuncSetAttribute(delta_scan_kernel, cudaFuncAttributeMaxDynamicSharedMemorySize,
                         SCAN_SMEM_FLOATS * 4);

    int nX4 = SEQ * DMODEL / 4;
    int nW4 = DMODEL * DMODEL / 4;
    dim3 tg(DMODEL / 64, SEQ / 128);   // (16, 16) = 256 CTAs

    split_kernel<<<(nX4 + 255) / 256, 256>>>(x, xhi, xlo, nX4);       // idx 0
    split_kernel<<<(nW4 + 255) / 256, 256>>>(Wq, wqhi, wqlo, nW4);    // 1
    split_kernel<<<(nW4 + 255) / 256, 256>>>(Wk, wkhi, wklo, nW4);    // 2
    split_kernel<<<(nW4 + 255) / 256, 256>>>(Wv, wvhi, wvlo, nW4);    // 3
    hgemm_nt<<<tg, 256, HG_SMEM>>>(xhi, xlo, wqhi, wqlo, qlin, SEQ, DMODEL, DMODEL); // 4 <- ncu
    hgemm_nt<<<tg, 256, HG_SMEM>>>(xhi, xlo, wkhi, wklo, klin, SEQ, DMODEL, DMODEL); // 5
    hgemm_nt<<<tg, 256, HG_SMEM>>>(xhi, xlo, wvhi, wvlo, vlin, SEQ, DMODEL, DMODEL); // 6
    split_kernel<<<(nW4 + 255) / 256, 256>>>(Wo, wohi, wolo, nW4);    // 7

    int nelem = SEQ * DMODEL;
    conv_silu_kernel<<<nelem / 256, 256>>>(qlin, conv_q, qb);
    conv_silu_kernel<<<nelem / 256, 256>>>(klin, conv_k, kb);
    conv_silu_kernel<<<nelem / 256, 256>>>(vlin, conv_v, vb);

    beta_gate_kernel<<<SEQ, 256>>>(x, Wb, gate_w, gate_b, log_tmp, eps_p, betab, probsb);
    l2norm_qk_kernel<<<SEQ * NH, 256>>>(qb, kb);

    chunk_prep_kernel<<<NH * NCHUNK, 256, CP_SMEM_FLOATS * 4>>>(qb, kb, vb, betab,
                                                                ub, wb, attnb);
    delta_scan_kernel<<<NH * 32, 256, SCAN_SMEM_FLOATS * 4>>>(qb, kb, wb, ub, attnb, db);

    combine_kernel<<<SEQ * NH, 256>>>(vb, db, probsb, fir_s, fir_m, fir_l, norm_w, mixb);

    split_kernel<<<(nX4 + 255) / 256, 256>>>(mixb, mixhi, mixlo, nX4);
    hgemm_nt<<<tg, 256, HG_SMEM>>>(mixhi, mixlo, wohi, wolo, out, SEQ, DMODEL, DMODEL);
}

// round 7
// speedup vs baseline: 1.0860x; 1.0157x over previous
#include <cuda_runtime.h>
#include <cuda_fp16.h>
#include <cuda_bf16.h>
#include <cstdint>
#include <math.h>

// Problem constants
#define SEQ    2048
#define DMODEL 1024
#define NH     4
#define DHEAD  256
#define NCHUNK 64
#define CSZ    32
#define NQKV   3072

// ---------------- scratch (device globals; allocation-free) ----------------
__device__ __align__(16) float g_qkvlin[SEQ * NQKV];
__device__ __align__(16) float g_q[SEQ * DMODEL];
__device__ __align__(16) float g_k[SEQ * DMODEL];
__device__ __align__(16) float g_v[SEQ * DMODEL];
__device__ __align__(16) float g_u[SEQ * DMODEL];
__device__ __align__(16) float g_w[SEQ * DMODEL];
__device__ __align__(16) float g_delta[SEQ * DMODEL];
__device__ __align__(16) float g_mix[SEQ * DMODEL];
__device__ __align__(16) float g_beta[SEQ * NH];
__device__ __align__(16) float g_probs[SEQ * NH * 5];
__device__ __align__(16) float g_attn[NH * NCHUNK * CSZ * CSZ];

// fp16 buffers: activations hi+lo, weights hi only
__device__ __align__(16) __half g_xh[SEQ * DMODEL];
__device__ __align__(16) __half g_xl[SEQ * DMODEL];
__device__ __align__(16) __half g_wqkv[NQKV * DMODEL];   // [Wq;Wk;Wv] rows
__device__ __align__(16) __half g_wo[DMODEL * DMODEL];
__device__ __align__(16) __half g_mixh[SEQ * DMODEL];
__device__ __align__(16) __half g_mixl[SEQ * DMODEL];

// ---------------- fp16 2-product tensor-core GEMM: C = A * B^T --------------
// A = Ah + Al (fp16 hi/lo of fp32 activations), B = Bh (fp16-rounded weights).
// Tile 128(M) x 64(N), K-chunk 32, cp.async double-buffer.
#define HG_STRIDE 80
#define HG_AT     (128 * HG_STRIDE)          // 10240 per A tile
#define HG_BT     (64 * HG_STRIDE)           // 5120  B tile
#define HG_BUFB   (2 * HG_AT + HG_BT)        // 25600: AH, AL, BH
#define HG_SMEM   (2 * HG_BUFB)              // 51200

__device__ __forceinline__ void mma_f16(float* acc, const unsigned* a,
                                        const unsigned* b) {
    asm volatile(
        "mma.sync.aligned.m16n8k16.row.col.f32.f16.f16.f32 "
        "{%0,%1,%2,%3}, {%4,%5,%6,%7}, {%8,%9}, {%0,%1,%2,%3};"
        : "+f"(acc[0]), "+f"(acc[1]), "+f"(acc[2]), "+f"(acc[3])
        : "r"(a[0]), "r"(a[1]), "r"(a[2]), "r"(a[3]), "r"(b[0]), "r"(b[1]));
}
__device__ __forceinline__ void cp16(unsigned saddr, const void* g) {
    asm volatile("cp.async.cg.shared.global [%0], [%1], 16;"
                 :: "r"(saddr), "l"(g) : "memory");
}

__global__ __launch_bounds__(256, 2) void hgemm_nt(const __half* __restrict__ Ah,
                                                   const __half* __restrict__ Al,
                                                   const __half* __restrict__ Bh,
                                                   float* __restrict__ C,
                                                   int M, int N, int K) {
    extern __shared__ __align__(16) char smem[];
    unsigned sbase;
    asm("{ .reg .u64 t; cvta.to.shared.u64 t, %1; cvt.u32.u64 %0, t; }"
        : "=r"(sbase) : "l"(smem));
    int tid = threadIdx.x;
    int warp = tid >> 5, lane = tid & 31;
    int wm = warp >> 2;          // 0..1 -> M offset 64
    int wn = warp & 3;           // 0..3 -> N offset 16
    int g = lane >> 2, t = lane & 3;
    int bm = blockIdx.y * 128, bn = blockIdx.x * 64;

    float acc[4][2][4];
#pragma unroll
    for (int mi = 0; mi < 4; mi++)
#pragma unroll
        for (int nj = 0; nj < 2; nj++)
#pragma unroll
            for (int r = 0; r < 4; r++) acc[mi][nj][r] = 0.f;

#define HG_ISSUE(k0, buf)                                                           \
    do {                                                                            \
        unsigned bb = sbase + (buf) * HG_BUFB;                                      \
        _Pragma("unroll")                                                           \
        for (int it = 0; it < 2; it++) {                                            \
            int idx = tid + it * 256;                                               \
            int row = idx >> 2, quad = idx & 3;                                     \
            unsigned so = bb + row * HG_STRIDE + quad * 16;                         \
            size_t ga = (size_t)(bm + row) * K + (k0) + quad * 8;                   \
            cp16(so, Ah + ga);                                                      \
            cp16(so + HG_AT, Al + ga);                                              \
        }                                                                           \
        {                                                                           \
            int row = tid >> 2, quad = tid & 3;                                     \
            unsigned so = bb + 2 * HG_AT + row * HG_STRIDE + quad * 16;             \
            size_t gb = (size_t)(bn + row) * K + (k0) + quad * 8;                   \
            cp16(so, Bh + gb);                                                      \
        }                                                                           \
        asm volatile("cp.async.commit_group;" ::: "memory");                        \
    } while (0)

    HG_ISSUE(0, 0);

    const int nch = K / 32;
    int buf = 0;
    for (int ch = 0; ch < nch; ch++) {
        if (ch + 1 < nch) {
            HG_ISSUE((ch + 1) * 32, buf ^ 1);
            asm volatile("cp.async.wait_group 1;" ::: "memory");
        } else {
            asm volatile("cp.async.wait_group 0;" ::: "memory");
        }
        __syncthreads();

        const char* AH = smem + buf * HG_BUFB;
        const char* AL = AH + HG_AT;
        const char* BH = AH + 2 * HG_AT;

#pragma unroll
        for (int ks = 0; ks < 2; ks++) {
            int kb = ks * 32;   // byte offset (16 halves)
            unsigned ah[4][4], al[4][4], bh[2][2];
#pragma unroll
            for (int mi = 0; mi < 4; mi++) {
                int r0 = wm * 64 + mi * 16 + g;
                ah[mi][0] = *(const unsigned*)(AH + r0 * HG_STRIDE + kb + t * 4);
                ah[mi][1] = *(const unsigned*)(AH + (r0 + 8) * HG_STRIDE + kb + t * 4);
                ah[mi][2] = *(const unsigned*)(AH + r0 * HG_STRIDE + kb + 16 + t * 4);
                ah[mi][3] = *(const unsigned*)(AH + (r0 + 8) * HG_STRIDE + kb + 16 + t * 4);
                al[mi][0] = *(const unsigned*)(AL + r0 * HG_STRIDE + kb + t * 4);
                al[mi][1] = *(const unsigned*)(AL + (r0 + 8) * HG_STRIDE + kb + t * 4);
                al[mi][2] = *(const unsigned*)(AL + r0 * HG_STRIDE + kb + 16 + t * 4);
                al[mi][3] = *(const unsigned*)(AL + (r0 + 8) * HG_STRIDE + kb + 16 + t * 4);
            }
#pragma unroll
            for (int nj = 0; nj < 2; nj++) {
                int n = wn * 16 + nj * 8 + g;
                bh[nj][0] = *(const unsigned*)(BH + n * HG_STRIDE + kb + t * 4);
                bh[nj][1] = *(const unsigned*)(BH + n * HG_STRIDE + kb + 16 + t * 4);
            }
#pragma unroll
            for (int mi = 0; mi < 4; mi++)
#pragma unroll
                for (int nj = 0; nj < 2; nj++) {
                    mma_f16(acc[mi][nj], ah[mi], bh[nj]);
                    mma_f16(acc[mi][nj], al[mi], bh[nj]);
                }
        }
        __syncthreads();
        buf ^= 1;
    }

#pragma unroll
    for (int mi = 0; mi < 4; mi++) {
        int row = bm + wm * 64 + mi * 16 + g;
#pragma unroll
        for (int nj = 0; nj < 2; nj++) {
            int col = bn + wn * 16 + nj * 8 + t * 2;
            *(float2*)(C + (size_t)row * N + col) =
                make_float2(acc[mi][nj][0], acc[mi][nj][1]);
            *(float2*)(C + (size_t)(row + 8) * N + col) =
                make_float2(acc[mi][nj][2], acc[mi][nj][3]);
        }
    }
#undef HG_ISSUE
}

// ---------------- fp32 -> fp16 hi/lo split (activations) -------------------
__global__ void split_kernel(const float* __restrict__ in,
                             __half* __restrict__ hi,
                             __half* __restrict__ lo, int n4) {
    int i = blockIdx.x * 256 + threadIdx.x;
    if (i >= n4) return;
    float4 v = ((const float4*)in)[i];
    float vv[4] = {v.x, v.y, v.z, v.w};
    __align__(8) __half h[4];
    __align__(8) __half l[4];
#pragma unroll
    for (int j = 0; j < 4; j++) {
        h[j] = __float2half_rn(vv[j]);
        l[j] = __float2half_rn(vv[j] - __half2float(h[j]));
    }
    ((uint2*)hi)[i] = *(uint2*)h;
    ((uint2*)lo)[i] = *(uint2*)l;
}

// ---------------- weights -> fp16 (hi only), QKV packed --------------------
__global__ void wsplit_kernel(const float* __restrict__ Wq,
                              const float* __restrict__ Wk,
                              const float* __restrict__ Wv,
                              const float* __restrict__ Wo,
                              __half* __restrict__ wqkv,
                              __half* __restrict__ wo) {
    int i = blockIdx.x * 256 + threadIdx.x;   // over 1M/4 float4
    const int n4 = DMODEL * DMODEL / 4;
    if (i >= n4) return;
    const float* srcs[4] = {Wq, Wk, Wv, Wo};
#pragma unroll
    for (int s = 0; s < 4; s++) {
        float4 v = ((const float4*)srcs[s])[i];
        __align__(8) __half h[4];
        h[0] = __float2half_rn(v.x); h[1] = __float2half_rn(v.y);
        h[2] = __float2half_rn(v.z); h[3] = __float2half_rn(v.w);
        if (s < 3) ((uint2*)wqkv)[s * n4 + i] = *(uint2*)h;
        else       ((uint2*)wo)[i] = *(uint2*)h;
    }
}

// ---------------- fused short conv (K=4, causal) + silu for q,k,v ----------
__global__ void conv3_silu_kernel(const float* __restrict__ qkvlin,
                                  const float* __restrict__ wq,
                                  const float* __restrict__ wk,
                                  const float* __restrict__ wv,
                                  float* __restrict__ qb,
                                  float* __restrict__ kb,
                                  float* __restrict__ vb) {
    int idx = blockIdx.x * 256 + threadIdx.x;   // SEQ*NQKV
    int c = idx % NQKV;
    int t = idx / NQKV;
    int which = c >> 10, cc = c & 1023;
    const float* w = (which == 0) ? wq : (which == 1) ? wk : wv;
    float acc = 0.f;
#pragma unroll
    for (int j = 0; j < 4; j++) {
        int tt = t + j - 3;
        if (tt >= 0) acc += qkvlin[tt * NQKV + c] * w[cc * 4 + j];
    }
    float s = acc / (1.f + expf(-acc));
    float* o = (which == 0) ? qb : (which == 1) ? kb : vb;
    o[t * DMODEL + cc] = s;
}

// ---------------- beta (sigmoid) + gate probs ------------------------------
__global__ void beta_gate_kernel(const float* __restrict__ x,
                                 const float* __restrict__ Wb,
                                 const float* __restrict__ gate_w,
                                 const float* __restrict__ gate_b,
                                 const float* __restrict__ log_temp,
                                 const float* __restrict__ eps_param,
                                 float* __restrict__ beta_out,
                                 float* __restrict__ probs_out) {
    int t = blockIdx.x;
    __shared__ float sx[DMODEL];
    __shared__ float sdot[24];
    int tid = threadIdx.x;
    for (int i = tid; i < DMODEL; i += 256) sx[i] = x[t * DMODEL + i];
    __syncthreads();
    int warp = tid >> 5, lane = tid & 31;
    for (int o = warp; o < 24; o += 8) {
        const float* wrow = (o < 4) ? (Wb + o * DMODEL) : (gate_w + (o - 4) * DMODEL);
        float s = 0.f;
        for (int i = lane; i < DMODEL; i += 32) s += sx[i] * wrow[i];
#pragma unroll
        for (int off = 16; off; off >>= 1) s += __shfl_xor_sync(0xffffffffu, s, off);
        if (lane == 0) sdot[o] = s;
    }
    __syncthreads();
    if (tid < NH) {
        int h = tid;
        beta_out[t * NH + h] = 1.f / (1.f + expf(-sdot[h]));
        float temp = expf(log_temp[h]);
        float lg[5], mx = -1e30f;
#pragma unroll
        for (int p = 0; p < 5; p++) {
            lg[p] = (sdot[4 + h * 5 + p] + gate_b[h * 5 + p]) / temp;
            mx = fmaxf(mx, lg[p]);
        }
        float se = 0.f;
#pragma unroll
        for (int p = 0; p < 5; p++) { lg[p] = expf(lg[p] - mx); se += lg[p]; }
        float eps = fminf(fmaxf(eps_param[h], 0.f), 0.2f);
#pragma unroll
        for (int p = 0; p < 5; p++)
            probs_out[(t * NH + h) * 5 + p] = lg[p] / se * (1.f - 5.f * eps) + eps;
    }
}

// ---------------- l2 norm of q,k over head dim (in place) ------------------
__global__ void l2norm_qk_kernel(float* __restrict__ q, float* __restrict__ k) {
    int row = blockIdx.x;
    int t = row >> 2, h = row & 3;
    int base = t * DMODEL + h * DHEAD;
    int d = threadIdx.x;
    float qv = q[base + d], kv = k[base + d];
    float sq = qv * qv, sk = kv * kv;
#pragma unroll
    for (int off = 16; off; off >>= 1) {
        sq += __shfl_xor_sync(0xffffffffu, sq, off);
        sk += __shfl_xor_sync(0xffffffffu, sk, off);
    }
    __shared__ float red[2][8];
    int warp = d >> 5, lane = d & 31;
    if (lane == 0) { red[0][warp] = sq; red[1][warp] = sk; }
    __syncthreads();
    float ssq = 0.f, ssk = 0.f;
#pragma unroll
    for (int i = 0; i < 8; i++) { ssq += red[0][i]; ssk += red[1][i]; }
    q[base + d] = qv * rsqrtf(ssq + 1e-6f);
    k[base + d] = kv * rsqrtf(ssk + 1e-6f);
}

// ---------------- per-chunk UT transform (parallel over chunks) ------------
#define CP_SMEM_FLOATS (2 * 32 * 257 + 2 * 32 * 33 + 32)
__global__ __launch_bounds__(256) void chunk_prep_kernel(const float* __restrict__ q,
                                                         const float* __restrict__ k,
                                                         const float* __restrict__ v,
                                                         const float* __restrict__ beta,
                                                         float* __restrict__ gu,
                                                         float* __restrict__ gw,
                                                         float* __restrict__ gattn) {
    extern __shared__ float smemf[];
    float (*sk)[257] = (float (*)[257])smemf;
    float (*sx)[257] = (float (*)[257])(smemf + 32 * 257);
    float (*sA)[33]  = (float (*)[33])(smemf + 2 * 32 * 257);
    float (*sT)[33]  = (float (*)[33])(smemf + 2 * 32 * 257 + 32 * 33);
    float* sbeta     = smemf + 2 * 32 * 257 + 2 * 32 * 33;

    int hb = blockIdx.x;
    int h = hb >> 6, ch = hb & 63;
    int t0 = ch * CSZ;
    int tid = threadIdx.x;

    for (int i = tid; i < CSZ * DHEAD; i += 256) {
        int r = i >> 8, d = i & 255;
        sk[r][d] = k[(t0 + r) * DMODEL + h * DHEAD + d];
    }
    if (tid < CSZ) sbeta[tid] = beta[(t0 + tid) * NH + h];
    __syncthreads();

    for (int p = tid; p < CSZ * CSZ; p += 256) {
        int i = p >> 5, j = p & 31;
        float a = 0.f;
        if (j < i) {
            float s = 0.f;
            for (int d = 0; d < DHEAD; d++) s += sk[i][d] * sk[j][d];
            a = -sbeta[i] * s;
        }
        sA[i][j] = a;
    }
    __syncthreads();

    if (tid < 32) {
        int col = tid;
        for (int i = 0; i < CSZ; i++) {
            float tv = (col == i) ? 1.f : 0.f;
            for (int j = 0; j < i; j++) tv += sA[i][j] * sT[j][col];
            sT[i][col] = tv;
            __syncwarp();
        }
    }
    __syncthreads();

    for (int i = tid; i < CSZ * DHEAD; i += 256) {
        int r = i >> 8, d = i & 255;
        sx[r][d] = v[(t0 + r) * DMODEL + h * DHEAD + d] * sbeta[r];
    }
    __syncthreads();
    {
        int d = tid;
        for (int i = 0; i < CSZ; i++) {
            float a = 0.f;
            for (int j = 0; j <= i; j++) a += sT[i][j] * sx[j][d];
            gu[(t0 + i) * DMODEL + h * DHEAD + d] = a;
        }
    }
    {
        int d = tid;
        for (int i = 0; i < CSZ; i++) {
            float a = 0.f;
            for (int j = 0; j <= i; j++) a += sT[i][j] * sbeta[j] * sk[j][d];
            gw[(t0 + i) * DMODEL + h * DHEAD + d] = a;
        }
    }
    __syncthreads();
    for (int i = tid; i < CSZ * DHEAD; i += 256) {
        int r = i >> 8, d = i & 255;
        sx[r][d] = q[(t0 + r) * DMODEL + h * DHEAD + d];
    }
    __syncthreads();
    for (int p = tid; p < CSZ * CSZ; p += 256) {
        int i = p >> 5, j = p & 31;
        float a = 0.f;
        if (j <= i) {
            float s = 0.f;
            for (int d = 0; d < DHEAD; d++) s += sx[i][d] * sk[j][d];
            a = s;
        }
        gattn[(hb * CSZ + i) * CSZ + j] = a;
    }
}

// ---------------- sequential chunk scan, parallel over (head, dv-slice) ----
#define SCAN_SMEM_FLOATS (3 * 32 * 256 + 256 * 9 + 256 + 256 + 1024)
__global__ __launch_bounds__(256) void delta_scan_kernel(const float* __restrict__ q,
                                                         const float* __restrict__ k,
                                                         const float* __restrict__ w,
                                                         const float* __restrict__ u,
                                                         const float* __restrict__ attn,
                                                         float* __restrict__ dout) {
    extern __shared__ float smemf[];
    float (*sq)[256]  = (float (*)[256])smemf;
    float (*skk)[256] = (float (*)[256])(smemf + 8192);
    float (*sw)[256]  = (float (*)[256])(smemf + 16384);
    float (*S)[9]     = (float (*)[9])(smemf + 24576);
    float* su   = smemf + 24576 + 2304;
    float* sua  = su + 256;
    float* satt = sua + 256;

    int b = blockIdx.x;
    int h = b >> 5, sl = b & 31;
    int tid = threadIdx.x;
    int r = tid >> 3, c = tid & 7;
    int cbase = h * DHEAD + sl * 8;

    float Sreg[8];
#pragma unroll
    for (int i = 0; i < 8; i++) Sreg[i] = 0.f;

    for (int ch = 0; ch < NCHUNK; ch++) {
        int t0 = ch * CSZ;
#pragma unroll
        for (int i = 0; i < 8; i++) S[tid][i] = Sreg[i];
        for (int i = tid; i < CSZ * DHEAD; i += 256) {
            int rr = i >> 8, d = i & 255;
            int gidx = (t0 + rr) * DMODEL + h * DHEAD + d;
            sq[rr][d]  = q[gidx];
            skk[rr][d] = k[gidx];
            sw[rr][d]  = w[gidx];
        }
        su[tid] = u[(t0 + r) * DMODEL + cbase + c];
        for (int i = tid; i < CSZ * CSZ; i += 256)
            satt[i] = attn[(h * NCHUNK + ch) * CSZ * CSZ + i];
        __syncthreads();

        float au = su[tid], ao = 0.f;
#pragma unroll 8
        for (int d = 0; d < DHEAD; d++) {
            float sval = S[d][c];
            au = fmaf(-sw[r][d], sval, au);
            ao = fmaf(sq[r][d], sval, ao);
        }
        sua[tid] = au;
        __syncthreads();
#pragma unroll
        for (int j = 0; j < CSZ; j++) ao = fmaf(satt[r * CSZ + j], sua[j * 8 + c], ao);
        dout[(t0 + r) * DMODEL + cbase + c] = ao;

#pragma unroll 8
        for (int j = 0; j < CSZ; j++) {
            float kv = skk[j][tid];
#pragma unroll
            for (int cc = 0; cc < 8; cc++) Sreg[cc] = fmaf(kv, sua[j * 8 + cc], Sreg[cc]);
        }
        __syncthreads();
    }
}

// ---------------- FIR(3/15/63) + gated mix + per-head RMSNorm --------------
__global__ void combine_kernel(const float* __restrict__ v,
                               const float* __restrict__ delta,
                               const float* __restrict__ probs,
                               const float* __restrict__ fs,
                               const float* __restrict__ fm,
                               const float* __restrict__ fl,
                               const float* __restrict__ normw,
                               float* __restrict__ out) {
    int row = blockIdx.x;
    int t = row >> 2, h = row & 3;
    int d = threadIdx.x;
    int cidx = h * DHEAD + d;
    const float* pb = probs + (t * NH + h) * 5;
    float p0 = pb[0], p1 = pb[1], p2 = pb[2], p3 = pb[3], p4 = pb[4];

    float ll = 0.f;
    for (int kk = 0; kk < 63; kk++) {
        int tt = t + kk - 62;
        if (tt >= 0) ll = fmaf(v[tt * DMODEL + cidx], fl[cidx * 63 + kk], ll);
    }
    float lm = 0.f;
#pragma unroll
    for (int kk = 0; kk < 15; kk++) {
        int tt = t + kk - 14;
        if (tt >= 0) lm = fmaf(v[tt * DMODEL + cidx], fm[cidx * 15 + kk], lm);
    }
    float ls = 0.f;
#pragma unroll
    for (int kk = 0; kk < 3; kk++) {
        int tt = t + kk - 2;
        if (tt >= 0) ls = fmaf(v[tt * DMODEL + cidx], fs[cidx * 3 + kk], ls);
    }
    float vcur = v[t * DMODEL + cidx];
    float mix = p0 * ls + p1 * lm + p2 * ll + p3 * delta[t * DMODEL + cidx] + p4 * vcur;

    float s = mix * mix;
#pragma unroll
    for (int off = 16; off; off >>= 1) s += __shfl_xor_sync(0xffffffffu, s, off);
    __shared__ float red[8];
    int warp = d >> 5, lane = d & 31;
    if (lane == 0) red[warp] = s;
    __syncthreads();
    float ms = 0.f;
#pragma unroll
    for (int i = 0; i < 8; i++) ms += red[i];
    out[t * DMODEL + cidx] = mix * rsqrtf(ms * (1.f / 256.f) + 1e-5f) * normw[d];
}

// ---------------- launch ---------------------------------------------------
extern "C" void kernel_launch(void* const* d_in, const int* in_sizes, int n_in,
                              void* d_out, int out_size) {
    const float* x       = (const float*)d_in[0];
    const float* Wq      = (const float*)d_in[1];
    const float* Wk      = (const float*)d_in[2];
    const float* Wv      = (const float*)d_in[3];
    const float* Wb      = (const float*)d_in[4];
    const float* conv_q  = (const float*)d_in[5];
    const float* conv_k  = (const float*)d_in[6];
    const float* conv_v  = (const float*)d_in[7];
    const float* fir_s   = (const float*)d_in[8];
    const float* fir_m   = (const float*)d_in[9];
    const float* fir_l   = (const float*)d_in[10];
    const float* gate_w  = (const float*)d_in[11];
    const float* gate_b  = (const float*)d_in[12];
    const float* log_tmp = (const float*)d_in[13];
    const float* eps_p   = (const float*)d_in[14];
    const float* norm_w  = (const float*)d_in[15];
    const float* Wo      = (const float*)d_in[16];
    float* out = (float*)d_out;

    float *qkvlin, *qb, *kb, *vb, *ub, *wb, *db, *mixb, *betab, *probsb, *attnb;
    cudaGetSymbolAddress((void**)&qkvlin, g_qkvlin);
    cudaGetSymbolAddress((void**)&qb,    g_q);
    cudaGetSymbolAddress((void**)&kb,    g_k);
    cudaGetSymbolAddress((void**)&vb,    g_v);
    cudaGetSymbolAddress((void**)&ub,    g_u);
    cudaGetSymbolAddress((void**)&wb,    g_w);
    cudaGetSymbolAddress((void**)&db,    g_delta);
    cudaGetSymbolAddress((void**)&mixb,  g_mix);
    cudaGetSymbolAddress((void**)&betab, g_beta);
    cudaGetSymbolAddress((void**)&probsb, g_probs);
    cudaGetSymbolAddress((void**)&attnb, g_attn);

    __half *xh, *xl, *wqkv, *wo, *mixh, *mixl;
    cudaGetSymbolAddress((void**)&xh, g_xh);
    cudaGetSymbolAddress((void**)&xl, g_xl);
    cudaGetSymbolAddress((void**)&wqkv, g_wqkv);
    cudaGetSymbolAddress((void**)&wo, g_wo);
    cudaGetSymbolAddress((void**)&mixh, g_mixh);
    cudaGetSymbolAddress((void**)&mixl, g_mixl);

    cudaFuncSetAttribute(hgemm_nt, cudaFuncAttributeMaxDynamicSharedMemorySize, HG_SMEM);
    cudaFuncSetAttribute(chunk_prep_kernel, cudaFuncAttributeMaxDynamicSharedMemorySize,
                         CP_SMEM_FLOATS * 4);
    cudaFuncSetAttribute(delta_scan_kernel, cudaFuncAttributeMaxDynamicSharedMemorySize,
                         SCAN_SMEM_FLOATS * 4);

    int nX4 = SEQ * DMODEL / 4;      // 524288
    int nW4 = DMODEL * DMODEL / 4;   // 262144

    // 0: activations split
    split_kernel<<<(nX4 + 255) / 256, 256>>>(x, xh, xl, nX4);
    // 1: all weights -> fp16 (QKV packed)
    wsplit_kernel<<<(nW4 + 255) / 256, 256>>>(Wq, Wk, Wv, Wo, wqkv, wo);
    // 2: beta + gate (only needs x)
    beta_gate_kernel<<<SEQ, 256>>>(x, Wb, gate_w, gate_b, log_tmp, eps_p, betab, probsb);
    // 3: fused QKV GEMM [2048,3072] <- ncu capture target
    dim3 tg3(NQKV / 64, SEQ / 128);  // (48, 16) = 768 CTAs
    hgemm_nt<<<tg3, 256, HG_SMEM>>>(xh, xl, wqkv, qkvlin, SEQ, NQKV, DMODEL);
    // 4: fused conv+silu
    conv3_silu_kernel<<<SEQ * NQKV / 256, 256>>>(qkvlin, conv_q, conv_k, conv_v,
                                                 qb, kb, vb);
    // 5
    l2norm_qk_kernel<<<SEQ * NH, 256>>>(qb, kb);
    // 6
    chunk_prep_kernel<<<NH * NCHUNK, 256, CP_SMEM_FLOATS * 4>>>(qb, kb, vb, betab,
                                                                ub, wb, attnb);
    // 7
    delta_scan_kernel<<<NH * 32, 256, SCAN_SMEM_FLOATS * 4>>>(qb, kb, wb, ub, attnb, db);
    // 8
    combine_kernel<<<SEQ * NH, 256>>>(vb, db, probsb, fir_s, fir_m, fir_l, norm_w, mixb);
    // 9
    split_kernel<<<(nX4 + 255) / 256, 256>>>(mixb, mixh, mixl, nX4);
    // 10: output GEMM
    dim3 tg1(DMODEL / 64, SEQ / 128);  // (16, 16)
    hgemm_nt<<<tg1, 256, HG_SMEM>>>(mixh, mixl, wo, out, SEQ, DMODEL, DMODEL);
}

// round 8
// speedup vs baseline: 2.0152x; 1.8557x over previous
#include <cuda_runtime.h>
#include <cuda_fp16.h>
#include <cuda_bf16.h>
#include <cstdint>
#include <math.h>

// Problem constants
#define SEQ    2048
#define DMODEL 1024
#define NH     4
#define DHEAD  256
#define NCHUNK 64
#define CSZ    32
#define NQKV   3072

// ---------------- scratch (device globals; allocation-free) ----------------
__device__ __align__(16) float g_qkvlin[SEQ * NQKV];
__device__ __align__(16) float g_q[SEQ * DMODEL];
__device__ __align__(16) float g_k[SEQ * DMODEL];
__device__ __align__(16) float g_v[SEQ * DMODEL];
__device__ __align__(16) float g_u[SEQ * DMODEL];
__device__ __align__(16) float g_w[SEQ * DMODEL];
__device__ __align__(16) float g_delta[SEQ * DMODEL];
__device__ __align__(16) float g_mix[SEQ * DMODEL];
__device__ __align__(16) float g_beta[SEQ * NH];
__device__ __align__(16) float g_probs[SEQ * NH * 5];
__device__ __align__(16) float g_attn[NH * NCHUNK * CSZ * CSZ];

// fp16 buffers: activations hi+lo, weights hi only
__device__ __align__(16) __half g_xh[SEQ * DMODEL];
__device__ __align__(16) __half g_xl[SEQ * DMODEL];
__device__ __align__(16) __half g_wqkv[NQKV * DMODEL];
__device__ __align__(16) __half g_wo[DMODEL * DMODEL];
__device__ __align__(16) __half g_mixh[SEQ * DMODEL];
__device__ __align__(16) __half g_mixl[SEQ * DMODEL];

// ---------------- fp16 2-product tensor-core GEMM: C = A * B^T --------------
#define HG_STRIDE 80
#define HG_AT     (128 * HG_STRIDE)
#define HG_BT     (64 * HG_STRIDE)
#define HG_BUFB   (2 * HG_AT + HG_BT)
#define HG_SMEM   (2 * HG_BUFB)

__device__ __forceinline__ void mma_f16(float* acc, const unsigned* a,
                                        const unsigned* b) {
    asm volatile(
        "mma.sync.aligned.m16n8k16.row.col.f32.f16.f16.f32 "
        "{%0,%1,%2,%3}, {%4,%5,%6,%7}, {%8,%9}, {%0,%1,%2,%3};"
        : "+f"(acc[0]), "+f"(acc[1]), "+f"(acc[2]), "+f"(acc[3])
        : "r"(a[0]), "r"(a[1]), "r"(a[2]), "r"(a[3]), "r"(b[0]), "r"(b[1]));
}
__device__ __forceinline__ void cp16(unsigned saddr, const void* g) {
    asm volatile("cp.async.cg.shared.global [%0], [%1], 16;"
                 :: "r"(saddr), "l"(g) : "memory");
}

__global__ __launch_bounds__(256, 2) void hgemm_nt(const __half* __restrict__ Ah,
                                                   const __half* __restrict__ Al,
                                                   const __half* __restrict__ Bh,
                                                   float* __restrict__ C,
                                                   int M, int N, int K) {
    extern __shared__ __align__(16) char smem[];
    unsigned sbase;
    asm("{ .reg .u64 t; cvta.to.shared.u64 t, %1; cvt.u32.u64 %0, t; }"
        : "=r"(sbase) : "l"(smem));
    int tid = threadIdx.x;
    int warp = tid >> 5, lane = tid & 31;
    int wm = warp >> 2, wn = warp & 3;
    int g = lane >> 2, t = lane & 3;
    int bm = blockIdx.y * 128, bn = blockIdx.x * 64;

    float acc[4][2][4];
#pragma unroll
    for (int mi = 0; mi < 4; mi++)
#pragma unroll
        for (int nj = 0; nj < 2; nj++)
#pragma unroll
            for (int r = 0; r < 4; r++) acc[mi][nj][r] = 0.f;

#define HG_ISSUE(k0, buf)                                                           \
    do {                                                                            \
        unsigned bb = sbase + (buf) * HG_BUFB;                                      \
        _Pragma("unroll")                                                           \
        for (int it = 0; it < 2; it++) {                                            \
            int idx = tid + it * 256;                                               \
            int row = idx >> 2, quad = idx & 3;                                     \
            unsigned so = bb + row * HG_STRIDE + quad * 16;                         \
            size_t ga = (size_t)(bm + row) * K + (k0) + quad * 8;                   \
            cp16(so, Ah + ga);                                                      \
            cp16(so + HG_AT, Al + ga);                                              \
        }                                                                           \
        {                                                                           \
            int row = tid >> 2, quad = tid & 3;                                     \
            unsigned so = bb + 2 * HG_AT + row * HG_STRIDE + quad * 16;             \
            size_t gb = (size_t)(bn + row) * K + (k0) + quad * 8;                   \
            cp16(so, Bh + gb);                                                      \
        }                                                                           \
        asm volatile("cp.async.commit_group;" ::: "memory");                        \
    } while (0)

    HG_ISSUE(0, 0);

    const int nch = K / 32;
    int buf = 0;
    for (int ch = 0; ch < nch; ch++) {
        if (ch + 1 < nch) {
            HG_ISSUE((ch + 1) * 32, buf ^ 1);
            asm volatile("cp.async.wait_group 1;" ::: "memory");
        } else {
            asm volatile("cp.async.wait_group 0;" ::: "memory");
        }
        __syncthreads();

        const char* AH = smem + buf * HG_BUFB;
        const char* AL = AH + HG_AT;
        const char* BH = AH + 2 * HG_AT;

#pragma unroll
        for (int ks = 0; ks < 2; ks++) {
            int kb = ks * 32;
            unsigned ah[4][4], al[4][4], bh[2][2];
#pragma unroll
            for (int mi = 0; mi < 4; mi++) {
                int r0 = wm * 64 + mi * 16 + g;
                ah[mi][0] = *(const unsigned*)(AH + r0 * HG_STRIDE + kb + t * 4);
                ah[mi][1] = *(const unsigned*)(AH + (r0 + 8) * HG_STRIDE + kb + t * 4);
                ah[mi][2] = *(const unsigned*)(AH + r0 * HG_STRIDE + kb + 16 + t * 4);
                ah[mi][3] = *(const unsigned*)(AH + (r0 + 8) * HG_STRIDE + kb + 16 + t * 4);
                al[mi][0] = *(const unsigned*)(AL + r0 * HG_STRIDE + kb + t * 4);
                al[mi][1] = *(const unsigned*)(AL + (r0 + 8) * HG_STRIDE + kb + t * 4);
                al[mi][2] = *(const unsigned*)(AL + r0 * HG_STRIDE + kb + 16 + t * 4);
                al[mi][3] = *(const unsigned*)(AL + (r0 + 8) * HG_STRIDE + kb + 16 + t * 4);
            }
#pragma unroll
            for (int nj = 0; nj < 2; nj++) {
                int n = wn * 16 + nj * 8 + g;
                bh[nj][0] = *(const unsigned*)(BH + n * HG_STRIDE + kb + t * 4);
                bh[nj][1] = *(const unsigned*)(BH + n * HG_STRIDE + kb + 16 + t * 4);
            }
#pragma unroll
            for (int mi = 0; mi < 4; mi++)
#pragma unroll
                for (int nj = 0; nj < 2; nj++) {
                    mma_f16(acc[mi][nj], ah[mi], bh[nj]);
                    mma_f16(acc[mi][nj], al[mi], bh[nj]);
                }
        }
        __syncthreads();
        buf ^= 1;
    }

#pragma unroll
    for (int mi = 0; mi < 4; mi++) {
        int row = bm + wm * 64 + mi * 16 + g;
#pragma unroll
        for (int nj = 0; nj < 2; nj++) {
            int col = bn + wn * 16 + nj * 8 + t * 2;
            *(float2*)(C + (size_t)row * N + col) =
                make_float2(acc[mi][nj][0], acc[mi][nj][1]);
            *(float2*)(C + (size_t)(row + 8) * N + col) =
                make_float2(acc[mi][nj][2], acc[mi][nj][3]);
        }
    }
#undef HG_ISSUE
}

// ---------------- fp32 -> fp16 hi/lo split (activations) -------------------
__global__ void split_kernel(const float* __restrict__ in,
                             __half* __restrict__ hi,
                             __half* __restrict__ lo, int n4) {
    int i = blockIdx.x * 256 + threadIdx.x;
    if (i >= n4) return;
    float4 v = ((const float4*)in)[i];
    float vv[4] = {v.x, v.y, v.z, v.w};
    __align__(8) __half h[4];
    __align__(8) __half l[4];
#pragma unroll
    for (int j = 0; j < 4; j++) {
        h[j] = __float2half_rn(vv[j]);
        l[j] = __float2half_rn(vv[j] - __half2float(h[j]));
    }
    ((uint2*)hi)[i] = *(uint2*)h;
    ((uint2*)lo)[i] = *(uint2*)l;
}

// ---------------- weights -> fp16 (hi only), QKV packed --------------------
__global__ void wsplit_kernel(const float* __restrict__ Wq,
                              const float* __restrict__ Wk,
                              const float* __restrict__ Wv,
                              const float* __restrict__ Wo,
                              __half* __restrict__ wqkv,
                              __half* __restrict__ wo) {
    int i = blockIdx.x * 256 + threadIdx.x;
    const int n4 = DMODEL * DMODEL / 4;
    if (i >= n4) return;
    const float* srcs[4] = {Wq, Wk, Wv, Wo};
#pragma unroll
    for (int s = 0; s < 4; s++) {
        float4 v = ((const float4*)srcs[s])[i];
        __align__(8) __half h[4];
        h[0] = __float2half_rn(v.x); h[1] = __float2half_rn(v.y);
        h[2] = __float2half_rn(v.z); h[3] = __float2half_rn(v.w);
        if (s < 3) ((uint2*)wqkv)[s * n4 + i] = *(uint2*)h;
        else       ((uint2*)wo)[i] = *(uint2*)h;
    }
}

// ---------------- fused short conv (K=4, causal) + silu for q,k,v ----------
__global__ void conv3_silu_kernel(const float* __restrict__ qkvlin,
                                  const float* __restrict__ wq,
                                  const float* __restrict__ wk,
                                  const float* __restrict__ wv,
                                  float* __restrict__ qb,
                                  float* __restrict__ kb,
                                  float* __restrict__ vb) {
    int idx = blockIdx.x * 256 + threadIdx.x;
    int c = idx % NQKV;
    int t = idx / NQKV;
    int which = c >> 10, cc = c & 1023;
    const float* w = (which == 0) ? wq : (which == 1) ? wk : wv;
    float acc = 0.f;
#pragma unroll
    for (int j = 0; j < 4; j++) {
        int tt = t + j - 3;
        if (tt >= 0) acc += qkvlin[tt * NQKV + c] * w[cc * 4 + j];
    }
    float s = acc / (1.f + expf(-acc));
    float* o = (which == 0) ? qb : (which == 1) ? kb : vb;
    o[t * DMODEL + cc] = s;
}

// ---------------- beta (sigmoid) + gate probs ------------------------------
__global__ void beta_gate_kernel(const float* __restrict__ x,
                                 const float* __restrict__ Wb,
                                 const float* __restrict__ gate_w,
                                 const float* __restrict__ gate_b,
                                 const float* __restrict__ log_temp,
                                 const float* __restrict__ eps_param,
                                 float* __restrict__ beta_out,
                                 float* __restrict__ probs_out) {
    int t = blockIdx.x;
    __shared__ float sx[DMODEL];
    __shared__ float sdot[24];
    int tid = threadIdx.x;
    for (int i = tid; i < DMODEL; i += 256) sx[i] = x[t * DMODEL + i];
    __syncthreads();
    int warp = tid >> 5, lane = tid & 31;
    for (int o = warp; o < 24; o += 8) {
        const float* wrow = (o < 4) ? (Wb + o * DMODEL) : (gate_w + (o - 4) * DMODEL);
        float s = 0.f;
        for (int i = lane; i < DMODEL; i += 32) s += sx[i] * wrow[i];
#pragma unroll
        for (int off = 16; off; off >>= 1) s += __shfl_xor_sync(0xffffffffu, s, off);
        if (lane == 0) sdot[o] = s;
    }
    __syncthreads();
    if (tid < NH) {
        int h = tid;
        beta_out[t * NH + h] = 1.f / (1.f + expf(-sdot[h]));
        float temp = expf(log_temp[h]);
        float lg[5], mx = -1e30f;
#pragma unroll
        for (int p = 0; p < 5; p++) {
            lg[p] = (sdot[4 + h * 5 + p] + gate_b[h * 5 + p]) / temp;
            mx = fmaxf(mx, lg[p]);
        }
        float se = 0.f;
#pragma unroll
        for (int p = 0; p < 5; p++) { lg[p] = expf(lg[p] - mx); se += lg[p]; }
        float eps = fminf(fmaxf(eps_param[h], 0.f), 0.2f);
#pragma unroll
        for (int p = 0; p < 5; p++)
            probs_out[(t * NH + h) * 5 + p] = lg[p] / se * (1.f - 5.f * eps) + eps;
    }
}

// ---------------- l2 norm of q,k over head dim (in place) ------------------
__global__ void l2norm_qk_kernel(float* __restrict__ q, float* __restrict__ k) {
    int row = blockIdx.x;
    int t = row >> 2, h = row & 3;
    int base = t * DMODEL + h * DHEAD;
    int d = threadIdx.x;
    float qv = q[base + d], kv = k[base + d];
    float sq = qv * qv, sk = kv * kv;
#pragma unroll
    for (int off = 16; off; off >>= 1) {
        sq += __shfl_xor_sync(0xffffffffu, sq, off);
        sk += __shfl_xor_sync(0xffffffffu, sk, off);
    }
    __shared__ float red[2][8];
    int warp = d >> 5, lane = d & 31;
    if (lane == 0) { red[0][warp] = sq; red[1][warp] = sk; }
    __syncthreads();
    float ssq = 0.f, ssk = 0.f;
#pragma unroll
    for (int i = 0; i < 8; i++) { ssq += red[0][i]; ssk += red[1][i]; }
    q[base + d] = qv * rsqrtf(ssq + 1e-6f);
    k[base + d] = kv * rsqrtf(ssk + 1e-6f);
}

// ---------------- per-chunk UT transform (parallel over chunks) ------------
// smem: sk[32][260], sx[32][260], sA[32][33], sT[32][33], sbeta[32]
#define CP_SMEM_FLOATS (2 * 32 * 260 + 2 * 32 * 33 + 32)
__global__ __launch_bounds__(256) void chunk_prep_kernel(const float* __restrict__ q,
                                                         const float* __restrict__ k,
                                                         const float* __restrict__ v,
                                                         const float* __restrict__ beta,
                                                         float* __restrict__ gu,
                                                         float* __restrict__ gw,
                                                         float* __restrict__ gattn) {
    extern __shared__ float smemf[];
    float (*sk)[260] = (float (*)[260])smemf;
    float (*sx)[260] = (float (*)[260])(smemf + 32 * 260);
    float (*sA)[33]  = (float (*)[33])(smemf + 2 * 32 * 260);
    float (*sT)[33]  = (float (*)[33])(smemf + 2 * 32 * 260 + 32 * 33);
    float* sbeta     = smemf + 2 * 32 * 260 + 2 * 32 * 33;

    int hb = blockIdx.x;
    int h = hb >> 6, ch = hb & 63;
    int t0 = ch * CSZ;
    int tid = threadIdx.x;

#pragma unroll
    for (int it = 0; it < 8; it++) {
        int i4 = tid + it * 256;
        int row = i4 >> 6, d4 = (i4 & 63) << 2;
        *(float4*)&sk[row][d4] =
            *(const float4*)(k + (size_t)(t0 + row) * DMODEL + h * DHEAD + d4);
    }
    if (tid < CSZ) sbeta[tid] = beta[(t0 + tid) * NH + h];
    __syncthreads();

    // A[i][j] = -beta_i * (k_i . k_j), j < i  (float4 dots)
#pragma unroll
    for (int p = tid; p < CSZ * CSZ; p += 256) {
        int i = p >> 5, j = p & 31;
        float a = 0.f;
        if (j < i) {
            float s = 0.f;
#pragma unroll 16
            for (int d4 = 0; d4 < DHEAD; d4 += 4) {
                float4 xx = *(const float4*)&sk[i][d4];
                float4 yy = *(const float4*)&sk[j][d4];
                s = fmaf(xx.x, yy.x, fmaf(xx.y, yy.y,
                    fmaf(xx.z, yy.z, fmaf(xx.w, yy.w, s))));
            }
            a = -sbeta[i] * s;
        }
        sA[i][j] = a;
    }
    __syncthreads();

    // T = (I - A)^{-1} forward substitution (warp 0; upper cols -> 0)
    if (tid < 32) {
        int col = tid;
        for (int i = 0; i < CSZ; i++) {
            float tv = (col == i) ? 1.f : 0.f;
            for (int j = 0; j < i; j++) tv += sA[i][j] * sT[j][col];
            sT[i][col] = tv;
            __syncwarp();
        }
    }
    __syncthreads();

    // sx = v * beta
#pragma unroll
    for (int it = 0; it < 8; it++) {
        int i4 = tid + it * 256;
        int row = i4 >> 6, d4 = (i4 & 63) << 2;
        float4 vv = *(const float4*)(v + (size_t)(t0 + row) * DMODEL + h * DHEAD + d4);
        float bb = sbeta[row];
        vv.x *= bb; vv.y *= bb; vv.z *= bb; vv.w *= bb;
        *(float4*)&sx[row][d4] = vv;
    }
    __syncthreads();

    // u = T @ (v*beta), w = T @ (k*beta)  (j-outer, register accumulators)
    {
        int d = tid;
        float acc[32];
#pragma unroll
        for (int i = 0; i < 32; i++) acc[i] = 0.f;
#pragma unroll
        for (int j = 0; j < 32; j++) {
            float xv = sx[j][d];
#pragma unroll
            for (int i = j; i < 32; i++) acc[i] = fmaf(sT[i][j], xv, acc[i]);
        }
#pragma unroll
        for (int i = 0; i < 32; i++)
            gu[(t0 + i) * DMODEL + h * DHEAD + d] = acc[i];
#pragma unroll
        for (int i = 0; i < 32; i++) acc[i] = 0.f;
#pragma unroll
        for (int j = 0; j < 32; j++) {
            float xv = sbeta[j] * sk[j][d];
#pragma unroll
            for (int i = j; i < 32; i++) acc[i] = fmaf(sT[i][j], xv, acc[i]);
        }
#pragma unroll
        for (int i = 0; i < 32; i++)
            gw[(t0 + i) * DMODEL + h * DHEAD + d] = acc[i];
    }
    __syncthreads();

    // load q into sx, then attn = tril(q k^T)
#pragma unroll
    for (int it = 0; it < 8; it++) {
        int i4 = tid + it * 256;
        int row = i4 >> 6, d4 = (i4 & 63) << 2;
        *(float4*)&sx[row][d4] =
            *(const float4*)(q + (size_t)(t0 + row) * DMODEL + h * DHEAD + d4);
    }
    __syncthreads();
#pragma unroll
    for (int p = tid; p < CSZ * CSZ; p += 256) {
        int i = p >> 5, j = p & 31;
        float a = 0.f;
        if (j <= i) {
            float s = 0.f;
#pragma unroll 16
            for (int d4 = 0; d4 < DHEAD; d4 += 4) {
                float4 xx = *(const float4*)&sx[i][d4];
                float4 yy = *(const float4*)&sk[j][d4];
                s = fmaf(xx.x, yy.x, fmaf(xx.y, yy.y,
                    fmaf(xx.z, yy.z, fmaf(xx.w, yy.w, s))));
            }
            a = s;
        }
        gattn[(hb * CSZ + i) * CSZ + j] = a;
    }
}

// ---------------- sequential chunk scan, parallel over (head, dv-slice) ----
// smem: sq/skk/sw[32][260], Sc[8][260] (S col-major), su[256], sua[256], satt[1024]
#define SCAN_SMEM_FLOATS (3 * 32 * 260 + 8 * 260 + 256 + 256 + 1024)
__global__ __launch_bounds__(256) void delta_scan_kernel(const float* __restrict__ q,
                                                         const float* __restrict__ k,
                                                         const float* __restrict__ w,
                                                         const float* __restrict__ u,
                                                         const float* __restrict__ attn,
                                                         float* __restrict__ dout) {
    extern __shared__ float smemf[];
    float (*sq)[260]  = (float (*)[260])smemf;
    float (*skk)[260] = (float (*)[260])(smemf + 32 * 260);
    float (*sw)[260]  = (float (*)[260])(smemf + 2 * 32 * 260);
    float (*Sc)[260]  = (float (*)[260])(smemf + 3 * 32 * 260);  // Sc[c][d]
    float* su   = smemf + 3 * 32 * 260 + 8 * 260;
    float* sua  = su + 256;
    float* satt = sua + 256;

    int b = blockIdx.x;
    int h = b >> 5, sl = b & 31;
    int tid = threadIdx.x;
    int r = tid >> 3, c = tid & 7;
    int cbase = h * DHEAD + sl * 8;

    float Sreg[8];
#pragma unroll
    for (int i = 0; i < 8; i++) Sreg[i] = 0.f;

    for (int ch = 0; ch < NCHUNK; ch++) {
        int t0 = ch * CSZ;
#pragma unroll
        for (int i = 0; i < 8; i++) Sc[i][tid] = Sreg[i];
#pragma unroll
        for (int it = 0; it < 8; it++) {
            int i4 = tid + it * 256;
            int row = i4 >> 6, d4 = (i4 & 63) << 2;
            size_t gidx = (size_t)(t0 + row) * DMODEL + h * DHEAD + d4;
            *(float4*)&sq[row][d4]  = *(const float4*)(q + gidx);
            *(float4*)&skk[row][d4] = *(const float4*)(k + gidx);
            *(float4*)&sw[row][d4]  = *(const float4*)(w + gidx);
        }
        su[tid] = u[(t0 + r) * DMODEL + cbase + c];
        *(float4*)&satt[tid * 4] =
            *(const float4*)(attn + (size_t)(h * NCHUNK + ch) * 1024 + tid * 4);
        __syncthreads();

        // u_adj = u - w@S ; o_partial = q@S  (float4 over d)
        float au = su[tid], ao = 0.f;
#pragma unroll 8
        for (int d4 = 0; d4 < DHEAD; d4 += 4) {
            float4 sv = *(const float4*)&Sc[c][d4];
            float4 wv = *(const float4*)&sw[r][d4];
            float4 qv = *(const float4*)&sq[r][d4];
            au = fmaf(-wv.x, sv.x, au);
            au = fmaf(-wv.y, sv.y, au);
            au = fmaf(-wv.z, sv.z, au);
            au = fmaf(-wv.w, sv.w, au);
            ao = fmaf(qv.x, sv.x, ao);
            ao = fmaf(qv.y, sv.y, ao);
            ao = fmaf(qv.z, sv.z, ao);
            ao = fmaf(qv.w, sv.w, ao);
        }
        sua[tid] = au;
        __syncthreads();

#pragma unroll
        for (int j4 = 0; j4 < CSZ; j4 += 4) {
            float4 at = *(const float4*)&satt[r * CSZ + j4];
            ao = fmaf(at.x, sua[(j4 + 0) * 8 + c], ao);
            ao = fmaf(at.y, sua[(j4 + 1) * 8 + c], ao);
            ao = fmaf(at.z, sua[(j4 + 2) * 8 + c], ao);
            ao = fmaf(at.w, sua[(j4 + 3) * 8 + c], ao);
        }
        dout[(t0 + r) * DMODEL + cbase + c] = ao;

        // S += k^T @ u_adj ; thread owns S row d=tid
#pragma unroll 8
        for (int j = 0; j < CSZ; j++) {
            float kv = skk[j][tid];
            float4 u0 = *(const float4*)&sua[j * 8];
            float4 u1 = *(const float4*)&sua[j * 8 + 4];
            Sreg[0] = fmaf(kv, u0.x, Sreg[0]);
            Sreg[1] = fmaf(kv, u0.y, Sreg[1]);
            Sreg[2] = fmaf(kv, u0.z, Sreg[2]);
            Sreg[3] = fmaf(kv, u0.w, Sreg[3]);
            Sreg[4] = fmaf(kv, u1.x, Sreg[4]);
            Sreg[5] = fmaf(kv, u1.y, Sreg[5]);
            Sreg[6] = fmaf(kv, u1.z, Sreg[6]);
            Sreg[7] = fmaf(kv, u1.w, Sreg[7]);
        }
        __syncthreads();
    }
}

// ---------------- FIR(3/15/63) + gated mix + per-head RMSNorm, t-tiled -----
// block = (t-tile of 16, head); smem stages v rows + all filter taps coalesced.
#define CT 16
#define VR (CT + 62)                 // 78 staged v rows
#define CMB_SMEM_FLOATS (256 * 81 + 256 * 81 + 80 + 8)
__global__ __launch_bounds__(256) void combine_kernel(const float* __restrict__ v,
                                                      const float* __restrict__ delta,
                                                      const float* __restrict__ probs,
                                                      const float* __restrict__ fs,
                                                      const float* __restrict__ fm,
                                                      const float* __restrict__ fl,
                                                      const float* __restrict__ normw,
                                                      float* __restrict__ out) {
    extern __shared__ float cs[];
    float (*vsm)[81] = (float (*)[81])cs;              // [d][L]
    float (*fsm)[81] = (float (*)[81])(cs + 256 * 81); // [d][0:63 fl |63:78 fm |78:81 fs]
    float* psm = cs + 2 * 256 * 81;                    // 16 x 5 probs
    float* red = psm + 80;

    int bid = blockIdx.x;
    int h = bid & 3;
    int tt0 = (bid >> 2) * CT;
    int tid = threadIdx.x;
    int d = tid;

    // stage filters (coalesced)
    const float* flh = fl + h * 256 * 63;
    for (int f = tid; f < 256 * 63; f += 256) {
        int dd = f / 63;
        fsm[dd][f - dd * 63] = flh[f];
    }
    const float* fmh = fm + h * 256 * 15;
    for (int f = tid; f < 256 * 15; f += 256) {
        int dd = f / 15;
        fsm[dd][63 + f - dd * 15] = fmh[f];
    }
    const float* fsh = fs + h * 256 * 3;
    for (int f = tid; f < 256 * 3; f += 256) {
        int dd = f / 3;
        fsm[dd][78 + f - dd * 3] = fsh[f];
    }
    // stage probs for the 16 timesteps
    if (tid < CT * 5)
        psm[tid] = probs[(tt0 * NH + h) * 5 + (tid / 5) * (NH * 5) + (tid % 5)];
    // stage v rows (coalesced LDG, transposed STS)
    for (int L = 0; L < VR; L++) {
        int tt = tt0 - 62 + L;
        vsm[tid][L] = (tt >= 0) ? v[(size_t)tt * DMODEL + h * DHEAD + tid] : 0.f;
    }
    __syncthreads();

    float aL[CT], aM[CT], aS[CT];
#pragma unroll
    for (int t = 0; t < CT; t++) { aL[t] = 0.f; aM[t] = 0.f; aS[t] = 0.f; }

    for (int kk = 0; kk < 63; kk++) {
        float fv = fsm[d][kk];
#pragma unroll
        for (int t = 0; t < CT; t++) aL[t] = fmaf(vsm[d][kk + t], fv, aL[t]);
    }
#pragma unroll
    for (int kk = 0; kk < 15; kk++) {
        float fv = fsm[d][63 + kk];
#pragma unroll
        for (int t = 0; t < CT; t++) aM[t] = fmaf(vsm[d][48 + kk + t], fv, aM[t]);
    }
#pragma unroll
    for (int kk = 0; kk < 3; kk++) {
        float fv = fsm[d][78 + kk];
#pragma unroll
        for (int t = 0; t < CT; t++) aS[t] = fmaf(vsm[d][60 + kk + t], fv, aS[t]);
    }

    float dlv[CT];
#pragma unroll
    for (int t = 0; t < CT; t++)
        dlv[t] = delta[(size_t)(tt0 + t) * DMODEL + h * DHEAD + d];
    float nw = normw[d];
    int lane = tid & 31, warp = tid >> 5;

#pragma unroll 1
    for (int t = 0; t < CT; t++) {
        float vcur = vsm[d][62 + t];
        const float* pb = psm + t * 5;
        float mix = pb[0] * aS[t] + pb[1] * aM[t] + pb[2] * aL[t] +
                    pb[3] * dlv[t] + pb[4] * vcur;
        float s = mix * mix;
#pragma unroll
        for (int off = 16; off; off >>= 1) s += __shfl_xor_sync(0xffffffffu, s, off);
        if (lane == 0) red[warp] = s;
        __syncthreads();
        float ms = 0.f;
#pragma unroll
        for (int i = 0; i < 8; i++) ms += red[i];
        out[(size_t)(tt0 + t) * DMODEL + h * DHEAD + d] =
            mix * rsqrtf(ms * (1.f / 256.f) + 1e-5f) * nw;
        __syncthreads();
    }
}

// ---------------- launch ---------------------------------------------------
extern "C" void kernel_launch(void* const* d_in, const int* in_sizes, int n_in,
                              void* d_out, int out_size) {
    const float* x       = (const float*)d_in[0];
    const float* Wq      = (const float*)d_in[1];
    const float* Wk      = (const float*)d_in[2];
    const float* Wv      = (const float*)d_in[3];
    const float* Wb      = (const float*)d_in[4];
    const float* conv_q  = (const float*)d_in[5];
    const float* conv_k  = (const float*)d_in[6];
    const float* conv_v  = (const float*)d_in[7];
    const float* fir_s   = (const float*)d_in[8];
    const float* fir_m   = (const float*)d_in[9];
    const float* fir_l   = (const float*)d_in[10];
    const float* gate_w  = (const float*)d_in[11];
    const float* gate_b  = (const float*)d_in[12];
    const float* log_tmp = (const float*)d_in[13];
    const float* eps_p   = (const float*)d_in[14];
    const float* norm_w  = (const float*)d_in[15];
    const float* Wo      = (const float*)d_in[16];
    float* out = (float*)d_out;

    float *qkvlin, *qb, *kb, *vb, *ub, *wb, *db, *mixb, *betab, *probsb, *attnb;
    cudaGetSymbolAddress((void**)&qkvlin, g_qkvlin);
    cudaGetSymbolAddress((void**)&qb,    g_q);
    cudaGetSymbolAddress((void**)&kb,    g_k);
    cudaGetSymbolAddress((void**)&vb,    g_v);
    cudaGetSymbolAddress((void**)&ub,    g_u);
    cudaGetSymbolAddress((void**)&wb,    g_w);
    cudaGetSymbolAddress((void**)&db,    g_delta);
    cudaGetSymbolAddress((void**)&mixb,  g_mix);
    cudaGetSymbolAddress((void**)&betab, g_beta);
    cudaGetSymbolAddress((void**)&probsb, g_probs);
    cudaGetSymbolAddress((void**)&attnb, g_attn);

    __half *xh, *xl, *wqkv, *wo, *mixh, *mixl;
    cudaGetSymbolAddress((void**)&xh, g_xh);
    cudaGetSymbolAddress((void**)&xl, g_xl);
    cudaGetSymbolAddress((void**)&wqkv, g_wqkv);
    cudaGetSymbolAddress((void**)&wo, g_wo);
    cudaGetSymbolAddress((void**)&mixh, g_mixh);
    cudaGetSymbolAddress((void**)&mixl, g_mixl);

    cudaFuncSetAttribute(hgemm_nt, cudaFuncAttributeMaxDynamicSharedMemorySize, HG_SMEM);
    cudaFuncSetAttribute(chunk_prep_kernel, cudaFuncAttributeMaxDynamicSharedMemorySize,
                         CP_SMEM_FLOATS * 4);
    cudaFuncSetAttribute(delta_scan_kernel, cudaFuncAttributeMaxDynamicSharedMemorySize,
                         SCAN_SMEM_FLOATS * 4);
    cudaFuncSetAttribute(combine_kernel, cudaFuncAttributeMaxDynamicSharedMemorySize,
                         CMB_SMEM_FLOATS * 4);

    int nX4 = SEQ * DMODEL / 4;
    int nW4 = DMODEL * DMODEL / 4;

    split_kernel<<<(nX4 + 255) / 256, 256>>>(x, xh, xl, nX4);                 // 0
    wsplit_kernel<<<(nW4 + 255) / 256, 256>>>(Wq, Wk, Wv, Wo, wqkv, wo);      // 1
    beta_gate_kernel<<<SEQ, 256>>>(x, Wb, gate_w, gate_b, log_tmp, eps_p,
                                   betab, probsb);                            // 2
    dim3 tg3(NQKV / 64, SEQ / 128);                                           // (48,16)
    hgemm_nt<<<tg3, 256, HG_SMEM>>>(xh, xl, wqkv, qkvlin, SEQ, NQKV, DMODEL); // 3 (ncu)
    conv3_silu_kernel<<<SEQ * NQKV / 256, 256>>>(qkvlin, conv_q, conv_k, conv_v,
                                                 qb, kb, vb);                 // 4
    l2norm_qk_kernel<<<SEQ * NH, 256>>>(qb, kb);                              // 5
    chunk_prep_kernel<<<NH * NCHUNK, 256, CP_SMEM_FLOATS * 4>>>(qb, kb, vb, betab,
                                                                ub, wb, attnb);
    delta_scan_kernel<<<NH * 32, 256, SCAN_SMEM_FLOATS * 4>>>(qb, kb, wb, ub,
                                                              attnb, db);
    combine_kernel<<<(SEQ / CT) * NH, 256, CMB_SMEM_FLOATS * 4>>>(
        vb, db, probsb, fir_s, fir_m, fir_l, norm_w, mixb);
    split_kernel<<<(nX4 + 255) / 256, 256>>>(mixb, mixh, mixl, nX4);
    dim3 tg1(DMODEL / 64, SEQ / 128);
    hgemm_nt<<<tg1, 256, HG_SMEM>>>(mixh, mixl, wo, out, SEQ, DMODEL, DMODEL);
}

// round 9
// speedup vs baseline: 2.2821x; 1.1324x over previous
#include <cuda_runtime.h>
#include <cuda_fp16.h>
#include <cuda_bf16.h>
#include <cstdint>
#include <math.h>

// Problem constants
#define SEQ    2048
#define DMODEL 1024
#define NH     4
#define DHEAD  256
#define NCHUNK 64
#define CSZ    32
#define NQKV   3072

// ---------------- scratch (device globals; allocation-free) ----------------
__device__ __align__(16) float g_qkvlin[SEQ * NQKV];
__device__ __align__(16) float g_q[SEQ * DMODEL];
__device__ __align__(16) float g_k[SEQ * DMODEL];
__device__ __align__(16) float g_v[SEQ * DMODEL];
__device__ __align__(16) float g_u[SEQ * DMODEL];
__device__ __align__(16) float g_w[SEQ * DMODEL];
__device__ __align__(16) float g_delta[SEQ * DMODEL];
__device__ __align__(16) float g_mix[SEQ * DMODEL];
__device__ __align__(16) float g_beta[SEQ * NH];
__device__ __align__(16) float g_probs[SEQ * NH * 5];
__device__ __align__(16) float g_attn[NH * NCHUNK * CSZ * CSZ];

// fp16 buffers: activations hi+lo, weights hi only
__device__ __align__(16) __half g_xh[SEQ * DMODEL];
__device__ __align__(16) __half g_xl[SEQ * DMODEL];
__device__ __align__(16) __half g_wqkv[NQKV * DMODEL];
__device__ __align__(16) __half g_wo[DMODEL * DMODEL];
__device__ __align__(16) __half g_mixh[SEQ * DMODEL];
__device__ __align__(16) __half g_mixl[SEQ * DMODEL];

// ---------------- helpers ---------------------------------------------------
__device__ __forceinline__ void mma_f16(float* acc, const unsigned* a,
                                        const unsigned* b) {
    asm volatile(
        "mma.sync.aligned.m16n8k16.row.col.f32.f16.f16.f32 "
        "{%0,%1,%2,%3}, {%4,%5,%6,%7}, {%8,%9}, {%0,%1,%2,%3};"
        : "+f"(acc[0]), "+f"(acc[1]), "+f"(acc[2]), "+f"(acc[3])
        : "r"(a[0]), "r"(a[1]), "r"(a[2]), "r"(a[3]), "r"(b[0]), "r"(b[1]));
}
__device__ __forceinline__ void cp16(unsigned saddr, const void* g) {
    asm volatile("cp.async.cg.shared.global [%0], [%1], 16;"
                 :: "r"(saddr), "l"(g) : "memory");
}
__device__ __forceinline__ void cp4(unsigned saddr, const void* g) {
    asm volatile("cp.async.ca.shared.global [%0], [%1], 4;"
                 :: "r"(saddr), "l"(g) : "memory");
}
__device__ __forceinline__ void ldsm4(unsigned* r, unsigned saddr) {
    asm volatile("ldmatrix.sync.aligned.m8n8.x4.shared.b16 {%0,%1,%2,%3}, [%4];"
                 : "=r"(r[0]), "=r"(r[1]), "=r"(r[2]), "=r"(r[3]) : "r"(saddr));
}

// ---------------- fp16 2-product tensor-core GEMM: C = A * B^T --------------
#define HG_STRIDE 80
#define HG_AT     (128 * HG_STRIDE)
#define HG_BT     (64 * HG_STRIDE)
#define HG_BUFB   (2 * HG_AT + HG_BT)
#define HG_SMEM   (2 * HG_BUFB)

__global__ __launch_bounds__(256, 2) void hgemm_nt(const __half* __restrict__ Ah,
                                                   const __half* __restrict__ Al,
                                                   const __half* __restrict__ Bh,
                                                   float* __restrict__ C,
                                                   int M, int N, int K) {
    extern __shared__ __align__(16) char smem[];
    unsigned sbase;
    asm("{ .reg .u64 t; cvta.to.shared.u64 t, %1; cvt.u32.u64 %0, t; }"
        : "=r"(sbase) : "l"(smem));
    int tid = threadIdx.x;
    int warp = tid >> 5, lane = tid & 31;
    int wm = warp >> 2, wn = warp & 3;
    int g = lane >> 2, t = lane & 3;
    int bm = blockIdx.y * 128, bn = blockIdx.x * 64;

    // ldmatrix per-thread source offsets
    unsigned lrow8 = (lane & 7) + ((lane >> 3) & 1) * 8;
    unsigned khalf = (lane >> 4) * 16;
    unsigned a_off = (unsigned)((wm * 64 + lrow8) * HG_STRIDE + khalf);
    unsigned b_off = (unsigned)(2 * HG_AT + (wn * 16 + lrow8) * HG_STRIDE + khalf);

    float acc[4][2][4];
#pragma unroll
    for (int mi = 0; mi < 4; mi++)
#pragma unroll
        for (int nj = 0; nj < 2; nj++)
#pragma unroll
            for (int r = 0; r < 4; r++) acc[mi][nj][r] = 0.f;

#define HG_ISSUE(k0, buf)                                                           \
    do {                                                                            \
        unsigned bb = sbase + (buf) * HG_BUFB;                                      \
        _Pragma("unroll")                                                           \
        for (int it = 0; it < 2; it++) {                                            \
            int idx = tid + it * 256;                                               \
            int row = idx >> 2, quad = idx & 3;                                     \
            unsigned so = bb + row * HG_STRIDE + quad * 16;                         \
            size_t ga = (size_t)(bm + row) * K + (k0) + quad * 8;                   \
            cp16(so, Ah + ga);                                                      \
            cp16(so + HG_AT, Al + ga);                                              \
        }                                                                           \
        {                                                                           \
            int row = tid >> 2, quad = tid & 3;                                     \
            unsigned so = bb + 2 * HG_AT + row * HG_STRIDE + quad * 16;             \
            size_t gb = (size_t)(bn + row) * K + (k0) + quad * 8;                   \
            cp16(so, Bh + gb);                                                      \
        }                                                                           \
        asm volatile("cp.async.commit_group;" ::: "memory");                        \
    } while (0)

    HG_ISSUE(0, 0);

    const int nch = K / 32;
    int buf = 0;
    for (int ch = 0; ch < nch; ch++) {
        if (ch + 1 < nch) {
            HG_ISSUE((ch + 1) * 32, buf ^ 1);
            asm volatile("cp.async.wait_group 1;" ::: "memory");
        } else {
            asm volatile("cp.async.wait_group 0;" ::: "memory");
        }
        __syncthreads();

        unsigned bb = sbase + buf * HG_BUFB;
#pragma unroll
        for (int ks = 0; ks < 2; ks++) {
            unsigned kb = ks * 32;
            unsigned ah[4][4], al[4][4], bq[4];
#pragma unroll
            for (int mi = 0; mi < 4; mi++) {
                unsigned ad = bb + a_off + mi * (16 * HG_STRIDE) + kb;
                ldsm4(ah[mi], ad);
                ldsm4(al[mi], ad + HG_AT);
            }
            ldsm4(bq, bb + b_off + kb);
            unsigned bh0[2] = {bq[0], bq[2]};
            unsigned bh1[2] = {bq[1], bq[3]};
#pragma unroll
            for (int mi = 0; mi < 4; mi++) {
                mma_f16(acc[mi][0], ah[mi], bh0);
                mma_f16(acc[mi][0], al[mi], bh0);
                mma_f16(acc[mi][1], ah[mi], bh1);
                mma_f16(acc[mi][1], al[mi], bh1);
            }
        }
        __syncthreads();
        buf ^= 1;
    }

#pragma unroll
    for (int mi = 0; mi < 4; mi++) {
        int row = bm + wm * 64 + mi * 16 + g;
#pragma unroll
        for (int nj = 0; nj < 2; nj++) {
            int col = bn + wn * 16 + nj * 8 + t * 2;
            *(float2*)(C + (size_t)row * N + col) =
                make_float2(acc[mi][nj][0], acc[mi][nj][1]);
            *(float2*)(C + (size_t)(row + 8) * N + col) =
                make_float2(acc[mi][nj][2], acc[mi][nj][3]);
        }
    }
#undef HG_ISSUE
}

// ---------------- fp32 -> fp16 hi/lo split (activations) -------------------
__global__ void split_kernel(const float* __restrict__ in,
                             __half* __restrict__ hi,
                             __half* __restrict__ lo, int n4) {
    int i = blockIdx.x * 256 + threadIdx.x;
    if (i >= n4) return;
    float4 v = ((const float4*)in)[i];
    float vv[4] = {v.x, v.y, v.z, v.w};
    __align__(8) __half h[4];
    __align__(8) __half l[4];
#pragma unroll
    for (int j = 0; j < 4; j++) {
        h[j] = __float2half_rn(vv[j]);
        l[j] = __float2half_rn(vv[j] - __half2float(h[j]));
    }
    ((uint2*)hi)[i] = *(uint2*)h;
    ((uint2*)lo)[i] = *(uint2*)l;
}

// ---------------- weights -> fp16 (hi only), QKV packed --------------------
__global__ void wsplit_kernel(const float* __restrict__ Wq,
                              const float* __restrict__ Wk,
                              const float* __restrict__ Wv,
                              const float* __restrict__ Wo,
                              __half* __restrict__ wqkv,
                              __half* __restrict__ wo) {
    int i = blockIdx.x * 256 + threadIdx.x;
    const int n4 = DMODEL * DMODEL / 4;
    if (i >= n4) return;
    const float* srcs[4] = {Wq, Wk, Wv, Wo};
#pragma unroll
    for (int s = 0; s < 4; s++) {
        float4 v = ((const float4*)srcs[s])[i];
        __align__(8) __half h[4];
        h[0] = __float2half_rn(v.x); h[1] = __float2half_rn(v.y);
        h[2] = __float2half_rn(v.z); h[3] = __float2half_rn(v.w);
        if (s < 3) ((uint2*)wqkv)[s * n4 + i] = *(uint2*)h;
        else       ((uint2*)wo)[i] = *(uint2*)h;
    }
}

// ---------------- fused short conv (K=4, causal) + silu for q,k,v ----------
__global__ void conv3_silu_kernel(const float* __restrict__ qkvlin,
                                  const float* __restrict__ wq,
                                  const float* __restrict__ wk,
                                  const float* __restrict__ wv,
                                  float* __restrict__ qb,
                                  float* __restrict__ kb,
                                  float* __restrict__ vb) {
    int idx = blockIdx.x * 256 + threadIdx.x;
    int c = idx % NQKV;
    int t = idx / NQKV;
    int which = c >> 10, cc = c & 1023;
    const float* w = (which == 0) ? wq : (which == 1) ? wk : wv;
    float acc = 0.f;
#pragma unroll
    for (int j = 0; j < 4; j++) {
        int tt = t + j - 3;
        if (tt >= 0) acc += qkvlin[tt * NQKV + c] * w[cc * 4 + j];
    }
    float s = acc / (1.f + expf(-acc));
    float* o = (which == 0) ? qb : (which == 1) ? kb : vb;
    o[t * DMODEL + cc] = s;
}

// ---------------- beta (sigmoid) + gate probs ------------------------------
__global__ void beta_gate_kernel(const float* __restrict__ x,
                                 const float* __restrict__ Wb,
                                 const float* __restrict__ gate_w,
                                 const float* __restrict__ gate_b,
                                 const float* __restrict__ log_temp,
                                 const float* __restrict__ eps_param,
                                 float* __restrict__ beta_out,
                                 float* __restrict__ probs_out) {
    int t = blockIdx.x;
    __shared__ float sx[DMODEL];
    __shared__ float sdot[24];
    int tid = threadIdx.x;
    for (int i = tid; i < DMODEL; i += 256) sx[i] = x[t * DMODEL + i];
    __syncthreads();
    int warp = tid >> 5, lane = tid & 31;
    for (int o = warp; o < 24; o += 8) {
        const float* wrow = (o < 4) ? (Wb + o * DMODEL) : (gate_w + (o - 4) * DMODEL);
        float s = 0.f;
        for (int i = lane; i < DMODEL; i += 32) s += sx[i] * wrow[i];
#pragma unroll
        for (int off = 16; off; off >>= 1) s += __shfl_xor_sync(0xffffffffu, s, off);
        if (lane == 0) sdot[o] = s;
    }
    __syncthreads();
    if (tid < NH) {
        int h = tid;
        beta_out[t * NH + h] = 1.f / (1.f + expf(-sdot[h]));
        float temp = expf(log_temp[h]);
        float lg[5], mx = -1e30f;
#pragma unroll
        for (int p = 0; p < 5; p++) {
            lg[p] = (sdot[4 + h * 5 + p] + gate_b[h * 5 + p]) / temp;
            mx = fmaxf(mx, lg[p]);
        }
        float se = 0.f;
#pragma unroll
        for (int p = 0; p < 5; p++) { lg[p] = expf(lg[p] - mx); se += lg[p]; }
        float eps = fminf(fmaxf(eps_param[h], 0.f), 0.2f);
#pragma unroll
        for (int p = 0; p < 5; p++)
            probs_out[(t * NH + h) * 5 + p] = lg[p] / se * (1.f - 5.f * eps) + eps;
    }
}

// ---------------- l2 norm of q,k over head dim (in place) ------------------
__global__ void l2norm_qk_kernel(float* __restrict__ q, float* __restrict__ k) {
    int row = blockIdx.x;
    int t = row >> 2, h = row & 3;
    int base = t * DMODEL + h * DHEAD;
    int d = threadIdx.x;
    float qv = q[base + d], kv = k[base + d];
    float sq = qv * qv, sk = kv * kv;
#pragma unroll
    for (int off = 16; off; off >>= 1) {
        sq += __shfl_xor_sync(0xffffffffu, sq, off);
        sk += __shfl_xor_sync(0xffffffffu, sk, off);
    }
    __shared__ float red[2][8];
    int warp = d >> 5, lane = d & 31;
    if (lane == 0) { red[0][warp] = sq; red[1][warp] = sk; }
    __syncthreads();
    float ssq = 0.f, ssk = 0.f;
#pragma unroll
    for (int i = 0; i < 8; i++) { ssq += red[0][i]; ssk += red[1][i]; }
    q[base + d] = qv * rsqrtf(ssq + 1e-6f);
    k[base + d] = kv * rsqrtf(ssk + 1e-6f);
}

// ---------------- per-chunk UT transform (parallel over chunks) ------------
#define CP_SMEM_FLOATS (2 * 32 * 260 + 2 * 32 * 33 + 32)
__global__ __launch_bounds__(256) void chunk_prep_kernel(const float* __restrict__ q,
                                                         const float* __restrict__ k,
                                                         const float* __restrict__ v,
                                                         const float* __restrict__ beta,
                                                         float* __restrict__ gu,
                                                         float* __restrict__ gw,
                                                         float* __restrict__ gattn) {
    extern __shared__ float smemf[];
    float (*sk)[260] = (float (*)[260])smemf;
    float (*sx)[260] = (float (*)[260])(smemf + 32 * 260);
    float (*sA)[33]  = (float (*)[33])(smemf + 2 * 32 * 260);
    float (*sT)[33]  = (float (*)[33])(smemf + 2 * 32 * 260 + 32 * 33);
    float* sbeta     = smemf + 2 * 32 * 260 + 2 * 32 * 33;

    int hb = blockIdx.x;
    int h = hb >> 6, ch = hb & 63;
    int t0 = ch * CSZ;
    int tid = threadIdx.x;

#pragma unroll
    for (int it = 0; it < 8; it++) {
        int i4 = tid + it * 256;
        int row = i4 >> 6, d4 = (i4 & 63) << 2;
        *(float4*)&sk[row][d4] =
            *(const float4*)(k + (size_t)(t0 + row) * DMODEL + h * DHEAD + d4);
    }
    if (tid < CSZ) sbeta[tid] = beta[(t0 + tid) * NH + h];
    __syncthreads();

#pragma unroll
    for (int p = tid; p < CSZ * CSZ; p += 256) {
        int i = p >> 5, j = p & 31;
        float a = 0.f;
        if (j < i) {
            float s = 0.f;
#pragma unroll 16
            for (int d4 = 0; d4 < DHEAD; d4 += 4) {
                float4 xx = *(const float4*)&sk[i][d4];
                float4 yy = *(const float4*)&sk[j][d4];
                s = fmaf(xx.x, yy.x, fmaf(xx.y, yy.y,
                    fmaf(xx.z, yy.z, fmaf(xx.w, yy.w, s))));
            }
            a = -sbeta[i] * s;
        }
        sA[i][j] = a;
    }
    __syncthreads();

    if (tid < 32) {
        int col = tid;
        for (int i = 0; i < CSZ; i++) {
            float tv = (col == i) ? 1.f : 0.f;
            for (int j = 0; j < i; j++) tv += sA[i][j] * sT[j][col];
            sT[i][col] = tv;
            __syncwarp();
        }
    }
    __syncthreads();

#pragma unroll
    for (int it = 0; it < 8; it++) {
        int i4 = tid + it * 256;
        int row = i4 >> 6, d4 = (i4 & 63) << 2;
        float4 vv = *(const float4*)(v + (size_t)(t0 + row) * DMODEL + h * DHEAD + d4);
        float bb = sbeta[row];
        vv.x *= bb; vv.y *= bb; vv.z *= bb; vv.w *= bb;
        *(float4*)&sx[row][d4] = vv;
    }
    __syncthreads();

    {
        int d = tid;
        float acc[32];
#pragma unroll
        for (int i = 0; i < 32; i++) acc[i] = 0.f;
#pragma unroll
        for (int j = 0; j < 32; j++) {
            float xv = sx[j][d];
#pragma unroll
            for (int i = j; i < 32; i++) acc[i] = fmaf(sT[i][j], xv, acc[i]);
        }
#pragma unroll
        for (int i = 0; i < 32; i++)
            gu[(t0 + i) * DMODEL + h * DHEAD + d] = acc[i];
#pragma unroll
        for (int i = 0; i < 32; i++) acc[i] = 0.f;
#pragma unroll
        for (int j = 0; j < 32; j++) {
            float xv = sbeta[j] * sk[j][d];
#pragma unroll
            for (int i = j; i < 32; i++) acc[i] = fmaf(sT[i][j], xv, acc[i]);
        }
#pragma unroll
        for (int i = 0; i < 32; i++)
            gw[(t0 + i) * DMODEL + h * DHEAD + d] = acc[i];
    }
    __syncthreads();

#pragma unroll
    for (int it = 0; it < 8; it++) {
        int i4 = tid + it * 256;
        int row = i4 >> 6, d4 = (i4 & 63) << 2;
        *(float4*)&sx[row][d4] =
            *(const float4*)(q + (size_t)(t0 + row) * DMODEL + h * DHEAD + d4);
    }
    __syncthreads();
#pragma unroll
    for (int p = tid; p < CSZ * CSZ; p += 256) {
        int i = p >> 5, j = p & 31;
        float a = 0.f;
        if (j <= i) {
            float s = 0.f;
#pragma unroll 16
            for (int d4 = 0; d4 < DHEAD; d4 += 4) {
                float4 xx = *(const float4*)&sx[i][d4];
                float4 yy = *(const float4*)&sk[j][d4];
                s = fmaf(xx.x, yy.x, fmaf(xx.y, yy.y,
                    fmaf(xx.z, yy.z, fmaf(xx.w, yy.w, s))));
            }
            a = s;
        }
        gattn[(hb * CSZ + i) * CSZ + j] = a;
    }
}

// ---------------- sequential chunk scan, cp.async double-buffered ----------
// smem (floats): q/k/w tiles x2 bufs (32x260 each), Sc[8][260], su[2][256],
// satt[2][1024], sua[256]
#define SD_TILE   (32 * 260)
#define SD_BUF    (3 * SD_TILE)                 // 24960
#define SD_SC     (2 * SD_BUF)                  // 49920
#define SD_SU     (SD_SC + 8 * 260)             // 52000
#define SD_SATT   (SD_SU + 2 * 256)             // 52512
#define SD_SUA    (SD_SATT + 2 * 1024)          // 54560
#define SCAN_SMEM_FLOATS (SD_SUA + 256)         // 54816
__global__ __launch_bounds__(256) void delta_scan_kernel(const float* __restrict__ q,
                                                         const float* __restrict__ k,
                                                         const float* __restrict__ w,
                                                         const float* __restrict__ u,
                                                         const float* __restrict__ attn,
                                                         float* __restrict__ dout) {
    extern __shared__ float smemf[];
    unsigned sb;
    asm("{ .reg .u64 t; cvta.to.shared.u64 t, %1; cvt.u32.u64 %0, t; }"
        : "=r"(sb) : "l"(smemf));

    int b = blockIdx.x;
    int h = b >> 5, sl = b & 31;
    int tid = threadIdx.x;
    int r = tid >> 3, c = tid & 7;
    int cbase = h * DHEAD + sl * 8;

#define SD_ISSUE(ch, bf)                                                            \
    do {                                                                            \
        int t0i = (ch) * CSZ;                                                       \
        unsigned qo = sb + ((bf) * SD_BUF) * 4;                                     \
        _Pragma("unroll")                                                           \
        for (int it = 0; it < 8; it++) {                                            \
            int i4 = tid + it * 256;                                                \
            int row = i4 >> 6, d4 = (i4 & 63) << 2;                                 \
            size_t gidx = (size_t)(t0i + row) * DMODEL + h * DHEAD + d4;            \
            unsigned so = qo + (row * 260 + d4) * 4;                                \
            cp16(so, q + gidx);                                                     \
            cp16(so + SD_TILE * 4, k + gidx);                                       \
            cp16(so + 2 * SD_TILE * 4, w + gidx);                                   \
        }                                                                           \
        cp4(sb + (SD_SU + (bf) * 256 + tid) * 4,                                    \
            u + (size_t)(t0i + r) * DMODEL + cbase + c);                            \
        cp16(sb + (SD_SATT + (bf) * 1024 + tid * 4) * 4,                            \
             attn + (size_t)(h * NCHUNK + (ch)) * 1024 + tid * 4);                  \
        asm volatile("cp.async.commit_group;" ::: "memory");                        \
    } while (0)

    float Sreg[8];
#pragma unroll
    for (int i = 0; i < 8; i++) Sreg[i] = 0.f;

    SD_ISSUE(0, 0);
    int buf = 0;
    for (int ch = 0; ch < NCHUNK; ch++) {
        if (ch + 1 < NCHUNK) {
            SD_ISSUE(ch + 1, buf ^ 1);
            asm volatile("cp.async.wait_group 1;" ::: "memory");
        } else {
            asm volatile("cp.async.wait_group 0;" ::: "memory");
        }
        // publish S (col-major Sc[c][d]) for this chunk
#pragma unroll
        for (int i = 0; i < 8; i++) smemf[SD_SC + i * 260 + tid] = Sreg[i];
        __syncthreads();

        const float* sq  = smemf + buf * SD_BUF;
        const float* skk = sq + SD_TILE;
        const float* sw  = sq + 2 * SD_TILE;
        const float* su  = smemf + SD_SU + buf * 256;
        const float* satt = smemf + SD_SATT + buf * 1024;
        float* sua = smemf + SD_SUA;

        float au = su[tid], ao = 0.f;
#pragma unroll 8
        for (int d4 = 0; d4 < DHEAD; d4 += 4) {
            float4 sv = *(const float4*)&smemf[SD_SC + c * 260 + d4];
            float4 wv = *(const float4*)&sw[r * 260 + d4];
            float4 qv = *(const float4*)&sq[r * 260 + d4];
            au = fmaf(-wv.x, sv.x, au);
            au = fmaf(-wv.y, sv.y, au);
            au = fmaf(-wv.z, sv.z, au);
            au = fmaf(-wv.w, sv.w, au);
            ao = fmaf(qv.x, sv.x, ao);
            ao = fmaf(qv.y, sv.y, ao);
            ao = fmaf(qv.z, sv.z, ao);
            ao = fmaf(qv.w, sv.w, ao);
        }
        sua[tid] = au;
        __syncthreads();

#pragma unroll
        for (int j4 = 0; j4 < CSZ; j4 += 4) {
            float4 at = *(const float4*)&satt[r * CSZ + j4];
            ao = fmaf(at.x, sua[(j4 + 0) * 8 + c], ao);
            ao = fmaf(at.y, sua[(j4 + 1) * 8 + c], ao);
            ao = fmaf(at.z, sua[(j4 + 2) * 8 + c], ao);
            ao = fmaf(at.w, sua[(j4 + 3) * 8 + c], ao);
        }
        dout[(size_t)(ch * CSZ + r) * DMODEL + cbase + c] = ao;

#pragma unroll 8
        for (int j = 0; j < CSZ; j++) {
            float kv = skk[j * 260 + tid];
            float4 u0 = *(const float4*)&sua[j * 8];
            float4 u1 = *(const float4*)&sua[j * 8 + 4];
            Sreg[0] = fmaf(kv, u0.x, Sreg[0]);
            Sreg[1] = fmaf(kv, u0.y, Sreg[1]);
            Sreg[2] = fmaf(kv, u0.z, Sreg[2]);
            Sreg[3] = fmaf(kv, u0.w, Sreg[3]);
            Sreg[4] = fmaf(kv, u1.x, Sreg[4]);
            Sreg[5] = fmaf(kv, u1.y, Sreg[5]);
            Sreg[6] = fmaf(kv, u1.z, Sreg[6]);
            Sreg[7] = fmaf(kv, u1.w, Sreg[7]);
        }
        __syncthreads();
        buf ^= 1;
    }
#undef SD_ISSUE
}

// ---------------- FIR(3/15/63) + gated mix + per-head RMSNorm, t-tiled -----
#define CT 16
#define VR (CT + 62)
#define CMB_SMEM_FLOATS (256 * 81 + 256 * 81 + 80 + 4096 + 16)
__global__ __launch_bounds__(256) void combine_kernel(const float* __restrict__ v,
                                                      const float* __restrict__ delta,
                                                      const float* __restrict__ probs,
                                                      const float* __restrict__ fs,
                                                      const float* __restrict__ fm,
                                                      const float* __restrict__ fl,
                                                      const float* __restrict__ normw,
                                                      float* __restrict__ out) {
    extern __shared__ float cs[];
    float (*vsm)[81] = (float (*)[81])cs;
    float (*fsm)[81] = (float (*)[81])(cs + 256 * 81);
    float* psm = cs + 2 * 256 * 81;
    float* sqm = psm + 80;       // 16 x 256 squared-mix
    float* red = sqm + 4096;     // 16 sums

    int bid = blockIdx.x;
    int h = bid & 3;
    int tt0 = (bid >> 2) * CT;
    int tid = threadIdx.x;
    int d = tid;

    const float* flh = fl + h * 256 * 63;
    for (int f = tid; f < 256 * 63; f += 256) {
        int dd = f / 63;
        fsm[dd][f - dd * 63] = flh[f];
    }
    const float* fmh = fm + h * 256 * 15;
    for (int f = tid; f < 256 * 15; f += 256) {
        int dd = f / 15;
        fsm[dd][63 + f - dd * 15] = fmh[f];
    }
    const float* fsh = fs + h * 256 * 3;
    for (int f = tid; f < 256 * 3; f += 256) {
        int dd = f / 3;
        fsm[dd][78 + f - dd * 3] = fsh[f];
    }
    if (tid < CT * 5)
        psm[tid] = probs[(tt0 * NH + h) * 5 + (tid / 5) * (NH * 5) + (tid % 5)];
    for (int L = 0; L < VR; L++) {
        int tt = tt0 - 62 + L;
        vsm[tid][L] = (tt >= 0) ? v[(size_t)tt * DMODEL + h * DHEAD + tid] : 0.f;
    }
    __syncthreads();

    float aL[CT], aM[CT], aS[CT];
#pragma unroll
    for (int t = 0; t < CT; t++) { aL[t] = 0.f; aM[t] = 0.f; aS[t] = 0.f; }

    for (int kk = 0; kk < 63; kk++) {
        float fv = fsm[d][kk];
#pragma unroll
        for (int t = 0; t < CT; t++) aL[t] = fmaf(vsm[d][kk + t], fv, aL[t]);
    }
#pragma unroll
    for (int kk = 0; kk < 15; kk++) {
        float fv = fsm[d][63 + kk];
#pragma unroll
        for (int t = 0; t < CT; t++) aM[t] = fmaf(vsm[d][48 + kk + t], fv, aM[t]);
    }
#pragma unroll
    for (int kk = 0; kk < 3; kk++) {
        float fv = fsm[d][78 + kk];
#pragma unroll
        for (int t = 0; t < CT; t++) aS[t] = fmaf(vsm[d][60 + kk + t], fv, aS[t]);
    }

    float mixv[CT];
#pragma unroll
    for (int t = 0; t < CT; t++) {
        float dlv = delta[(size_t)(tt0 + t) * DMODEL + h * DHEAD + d];
        const float* pb = psm + t * 5;
        float vcur = vsm[d][62 + t];
        mixv[t] = pb[0] * aS[t] + pb[1] * aM[t] + pb[2] * aL[t] +
                  pb[3] * dlv + pb[4] * vcur;
        sqm[t * 256 + d] = mixv[t] * mixv[t];
    }
    __syncthreads();

    int lane = tid & 31, warp = tid >> 5;
#pragma unroll
    for (int tt = warp; tt < CT; tt += 8) {
        float s = 0.f;
#pragma unroll
        for (int i = lane; i < 256; i += 32) s += sqm[tt * 256 + i];
#pragma unroll
        for (int off = 16; off; off >>= 1) s += __shfl_xor_sync(0xffffffffu, s, off);
        if (lane == 0) red[tt] = s;
    }
    __syncthreads();

    float nw = normw[d];
#pragma unroll
    for (int t = 0; t < CT; t++) {
        out[(size_t)(tt0 + t) * DMODEL + h * DHEAD + d] =
            mixv[t] * rsqrtf(red[t] * (1.f / 256.f) + 1e-5f) * nw;
    }
}

// ---------------- launch ---------------------------------------------------
extern "C" void kernel_launch(void* const* d_in, const int* in_sizes, int n_in,
                              void* d_out, int out_size) {
    const float* x       = (const float*)d_in[0];
    const float* Wq      = (const float*)d_in[1];
    const float* Wk      = (const float*)d_in[2];
    const float* Wv      = (const float*)d_in[3];
    const float* Wb      = (const float*)d_in[4];
    const float* conv_q  = (const float*)d_in[5];
    const float* conv_k  = (const float*)d_in[6];
    const float* conv_v  = (const float*)d_in[7];
    const float* fir_s   = (const float*)d_in[8];
    const float* fir_m   = (const float*)d_in[9];
    const float* fir_l   = (const float*)d_in[10];
    const float* gate_w  = (const float*)d_in[11];
    const float* gate_b  = (const float*)d_in[12];
    const float* log_tmp = (const float*)d_in[13];
    const float* eps_p   = (const float*)d_in[14];
    const float* norm_w  = (const float*)d_in[15];
    const float* Wo      = (const float*)d_in[16];
    float* out = (float*)d_out;

    float *qkvlin, *qb, *kb, *vb, *ub, *wb, *db, *mixb, *betab, *probsb, *attnb;
    cudaGetSymbolAddress((void**)&qkvlin, g_qkvlin);
    cudaGetSymbolAddress((void**)&qb,    g_q);
    cudaGetSymbolAddress((void**)&kb,    g_k);
    cudaGetSymbolAddress((void**)&vb,    g_v);
    cudaGetSymbolAddress((void**)&ub,    g_u);
    cudaGetSymbolAddress((void**)&wb,    g_w);
    cudaGetSymbolAddress((void**)&db,    g_delta);
    cudaGetSymbolAddress((void**)&mixb,  g_mix);
    cudaGetSymbolAddress((void**)&betab, g_beta);
    cudaGetSymbolAddress((void**)&probsb, g_probs);
    cudaGetSymbolAddress((void**)&attnb, g_attn);

    __half *xh, *xl, *wqkv, *wo, *mixh, *mixl;
    cudaGetSymbolAddress((void**)&xh, g_xh);
    cudaGetSymbolAddress((void**)&xl, g_xl);
    cudaGetSymbolAddress((void**)&wqkv, g_wqkv);
    cudaGetSymbolAddress((void**)&wo, g_wo);
    cudaGetSymbolAddress((void**)&mixh, g_mixh);
    cudaGetSymbolAddress((void**)&mixl, g_mixl);

    cudaFuncSetAttribute(hgemm_nt, cudaFuncAttributeMaxDynamicSharedMemorySize, HG_SMEM);
    cudaFuncSetAttribute(chunk_prep_kernel, cudaFuncAttributeMaxDynamicSharedMemorySize,
                         CP_SMEM_FLOATS * 4);
    cudaFuncSetAttribute(delta_scan_kernel, cudaFuncAttributeMaxDynamicSharedMemorySize,
                         SCAN_SMEM_FLOATS * 4);
    cudaFuncSetAttribute(combine_kernel, cudaFuncAttributeMaxDynamicSharedMemorySize,
                         CMB_SMEM_FLOATS * 4);

    int nX4 = SEQ * DMODEL / 4;
    int nW4 = DMODEL * DMODEL / 4;

    split_kernel<<<(nX4 + 255) / 256, 256>>>(x, xh, xl, nX4);                 // 0
    wsplit_kernel<<<(nW4 + 255) / 256, 256>>>(Wq, Wk, Wv, Wo, wqkv, wo);      // 1
    beta_gate_kernel<<<SEQ, 256>>>(x, Wb, gate_w, gate_b, log_tmp, eps_p,
                                   betab, probsb);                            // 2
    dim3 tg3(NQKV / 64, SEQ / 128);
    hgemm_nt<<<tg3, 256, HG_SMEM>>>(xh, xl, wqkv, qkvlin, SEQ, NQKV, DMODEL); // 3 (ncu)
    conv3_silu_kernel<<<SEQ * NQKV / 256, 256>>>(qkvlin, conv_q, conv_k, conv_v,
                                                 qb, kb, vb);                 // 4
    l2norm_qk_kernel<<<SEQ * NH, 256>>>(qb, kb);                              // 5
    chunk_prep_kernel<<<NH * NCHUNK, 256, CP_SMEM_FLOATS * 4>>>(qb, kb, vb, betab,
                                                                ub, wb, attnb);
    delta_scan_kernel<<<NH * 32, 256, SCAN_SMEM_FLOATS * 4>>>(qb, kb, wb, ub,
                                                              attnb, db);
    combine_kernel<<<(SEQ / CT) * NH, 256, CMB_SMEM_FLOATS * 4>>>(
        vb, db, probsb, fir_s, fir_m, fir_l, norm_w, mixb);
    split_kernel<<<(nX4 + 255) / 256, 256>>>(mixb, mixh, mixl, nX4);
    dim3 tg1(DMODEL / 64, SEQ / 128);
    hgemm_nt<<<tg1, 256, HG_SMEM>>>(mixh, mixl, wo, out, SEQ, DMODEL, DMODEL);
}

// round 10
// speedup vs baseline: 2.3980x; 1.0508x over previous
#include <cuda_runtime.h>
#include <cuda_fp16.h>
#include <cuda_bf16.h>
#include <cstdint>
#include <math.h>

// Problem constants
#define SEQ    2048
#define DMODEL 1024
#define NH     4
#define DHEAD  256
#define NCHUNK 64
#define CSZ    32
#define NQKV   3072

// ---------------- scratch (device globals; allocation-free) ----------------
__device__ __align__(16) float g_qkvlin[SEQ * NQKV];
__device__ __align__(16) float g_q[SEQ * DMODEL];
__device__ __align__(16) float g_k[SEQ * DMODEL];
__device__ __align__(16) float g_v[SEQ * DMODEL];
__device__ __align__(16) float g_u[SEQ * DMODEL];
__device__ __align__(16) float g_w[SEQ * DMODEL];
__device__ __align__(16) float g_delta[SEQ * DMODEL];
__device__ __align__(16) float g_beta[SEQ * NH];
__device__ __align__(16) float g_probs[SEQ * NH * 5];
__device__ __align__(16) float g_attn[NH * NCHUNK * CSZ * CSZ];

// fp16 buffers: activations hi+lo, weights hi only
__device__ __align__(16) __half g_xh[SEQ * DMODEL];
__device__ __align__(16) __half g_xl[SEQ * DMODEL];
__device__ __align__(16) __half g_wqkv[NQKV * DMODEL];
__device__ __align__(16) __half g_wo[DMODEL * DMODEL];
__device__ __align__(16) __half g_mixh[SEQ * DMODEL];
__device__ __align__(16) __half g_mixl[SEQ * DMODEL];

// ---------------- helpers ---------------------------------------------------
__device__ __forceinline__ void mma_f16(float* acc, const unsigned* a,
                                        const unsigned* b) {
    asm volatile(
        "mma.sync.aligned.m16n8k16.row.col.f32.f16.f16.f32 "
        "{%0,%1,%2,%3}, {%4,%5,%6,%7}, {%8,%9}, {%0,%1,%2,%3};"
        : "+f"(acc[0]), "+f"(acc[1]), "+f"(acc[2]), "+f"(acc[3])
        : "r"(a[0]), "r"(a[1]), "r"(a[2]), "r"(a[3]), "r"(b[0]), "r"(b[1]));
}
__device__ __forceinline__ void cp16(unsigned saddr, const void* g) {
    asm volatile("cp.async.cg.shared.global [%0], [%1], 16;"
                 :: "r"(saddr), "l"(g) : "memory");
}
__device__ __forceinline__ void cp4(unsigned saddr, const void* g) {
    asm volatile("cp.async.ca.shared.global [%0], [%1], 4;"
                 :: "r"(saddr), "l"(g) : "memory");
}
__device__ __forceinline__ void ldsm4(unsigned* r, unsigned saddr) {
    asm volatile("ldmatrix.sync.aligned.m8n8.x4.shared.b16 {%0,%1,%2,%3}, [%4];"
                 : "=r"(r[0]), "=r"(r[1]), "=r"(r[2]), "=r"(r[3]) : "r"(saddr));
}

// ---------------- fp16 2-product tensor-core GEMM: C = A * B^T --------------
// CTA tile 128x128, warp tile 64x32 (wm 0..1, wn 0..3), K-chunk 32,
// cp.async double-buffer, ldmatrix fragments.
#define HG_STRIDE 80
#define HG_AT     (128 * HG_STRIDE)          // 10240 (A rows)
#define HG_BT     (128 * HG_STRIDE)          // 10240 (B rows)
#define HG_BUFB   (2 * HG_AT + HG_BT)        // 30720: AH, AL, BH
#define HG_SMEM   (2 * HG_BUFB)              // 61440

__global__ __launch_bounds__(256, 1) void hgemm_nt(const __half* __restrict__ Ah,
                                                   const __half* __restrict__ Al,
                                                   const __half* __restrict__ Bh,
                                                   float* __restrict__ C,
                                                   int M, int N, int K) {
    extern __shared__ __align__(16) char smem[];
    unsigned sbase;
    asm("{ .reg .u64 t; cvta.to.shared.u64 t, %1; cvt.u32.u64 %0, t; }"
        : "=r"(sbase) : "l"(smem));
    int tid = threadIdx.x;
    int warp = tid >> 5, lane = tid & 31;
    int wm = warp >> 2, wn = warp & 3;
    int g = lane >> 2, t = lane & 3;
    int bm = blockIdx.y * 128, bn = blockIdx.x * 128;

    unsigned lrow8 = (lane & 7) + ((lane >> 3) & 1) * 8;
    unsigned khalf = (lane >> 4) * 16;
    unsigned a_off = (unsigned)((wm * 64 + lrow8) * HG_STRIDE + khalf);
    unsigned b_off = (unsigned)(2 * HG_AT + (wn * 32 + lrow8) * HG_STRIDE + khalf);

    float acc[4][4][4];
#pragma unroll
    for (int mi = 0; mi < 4; mi++)
#pragma unroll
        for (int nj = 0; nj < 4; nj++)
#pragma unroll
            for (int r = 0; r < 4; r++) acc[mi][nj][r] = 0.f;

#define HG_ISSUE(k0, buf)                                                           \
    do {                                                                            \
        unsigned bb = sbase + (buf) * HG_BUFB;                                      \
        _Pragma("unroll")                                                           \
        for (int it = 0; it < 2; it++) {                                            \
            int idx = tid + it * 256;                                               \
            int row = idx >> 2, quad = idx & 3;                                     \
            unsigned so = bb + row * HG_STRIDE + quad * 16;                         \
            size_t ga = (size_t)(bm + row) * K + (k0) + quad * 8;                   \
            cp16(so, Ah + ga);                                                      \
            cp16(so + HG_AT, Al + ga);                                              \
        }                                                                           \
        _Pragma("unroll")                                                           \
        for (int it = 0; it < 2; it++) {                                            \
            int idx = tid + it * 256;                                               \
            int row = idx >> 2, quad = idx & 3;                                     \
            unsigned so = bb + 2 * HG_AT + row * HG_STRIDE + quad * 16;             \
            size_t gb = (size_t)(bn + row) * K + (k0) + quad * 8;                   \
            cp16(so, Bh + gb);                                                      \
        }                                                                           \
        asm volatile("cp.async.commit_group;" ::: "memory");                        \
    } while (0)

    HG_ISSUE(0, 0);

    const int nch = K / 32;
    int buf = 0;
    for (int ch = 0; ch < nch; ch++) {
        if (ch + 1 < nch) {
            HG_ISSUE((ch + 1) * 32, buf ^ 1);
            asm volatile("cp.async.wait_group 1;" ::: "memory");
        } else {
            asm volatile("cp.async.wait_group 0;" ::: "memory");
        }
        __syncthreads();

        unsigned bb = sbase + buf * HG_BUFB;
#pragma unroll
        for (int ks = 0; ks < 2; ks++) {
            unsigned kb = ks * 32;
            unsigned ah[4][4], al[4][4], bq0[4], bq1[4];
#pragma unroll
            for (int mi = 0; mi < 4; mi++) {
                unsigned ad = bb + a_off + mi * (16 * HG_STRIDE) + kb;
                ldsm4(ah[mi], ad);
                ldsm4(al[mi], ad + HG_AT);
            }
            ldsm4(bq0, bb + b_off + kb);
            ldsm4(bq1, bb + b_off + 16 * HG_STRIDE + kb);
            unsigned bf[4][2] = {{bq0[0], bq0[2]}, {bq0[1], bq0[3]},
                                 {bq1[0], bq1[2]}, {bq1[1], bq1[3]}};
#pragma unroll
            for (int mi = 0; mi < 4; mi++)
#pragma unroll
                for (int nj = 0; nj < 4; nj++) {
                    mma_f16(acc[mi][nj], ah[mi], bf[nj]);
                    mma_f16(acc[mi][nj], al[mi], bf[nj]);
                }
        }
        __syncthreads();
        buf ^= 1;
    }

#pragma unroll
    for (int mi = 0; mi < 4; mi++) {
        int row = bm + wm * 64 + mi * 16 + g;
#pragma unroll
        for (int nj = 0; nj < 4; nj++) {
            int col = bn + wn * 32 + nj * 8 + t * 2;
            *(float2*)(C + (size_t)row * N + col) =
                make_float2(acc[mi][nj][0], acc[mi][nj][1]);
            *(float2*)(C + (size_t)(row + 8) * N + col) =
                make_float2(acc[mi][nj][2], acc[mi][nj][3]);
        }
    }
#undef HG_ISSUE
}

// ---------------- fp32 -> fp16 hi/lo split (activations) -------------------
__global__ void split_kernel(const float* __restrict__ in,
                             __half* __restrict__ hi,
                             __half* __restrict__ lo, int n4) {
    int i = blockIdx.x * 256 + threadIdx.x;
    if (i >= n4) return;
    float4 v = ((const float4*)in)[i];
    float vv[4] = {v.x, v.y, v.z, v.w};
    __align__(8) __half h[4];
    __align__(8) __half l[4];
#pragma unroll
    for (int j = 0; j < 4; j++) {
        h[j] = __float2half_rn(vv[j]);
        l[j] = __float2half_rn(vv[j] - __half2float(h[j]));
    }
    ((uint2*)hi)[i] = *(uint2*)h;
    ((uint2*)lo)[i] = *(uint2*)l;
}

// ---------------- weights -> fp16 (hi only), QKV packed --------------------
__global__ void wsplit_kernel(const float* __restrict__ Wq,
                              const float* __restrict__ Wk,
                              const float* __restrict__ Wv,
                              const float* __restrict__ Wo,
                              __half* __restrict__ wqkv,
                              __half* __restrict__ wo) {
    int i = blockIdx.x * 256 + threadIdx.x;
    const int n4 = DMODEL * DMODEL / 4;
    if (i >= n4) return;
    const float* srcs[4] = {Wq, Wk, Wv, Wo};
#pragma unroll
    for (int s = 0; s < 4; s++) {
        float4 v = ((const float4*)srcs[s])[i];
        __align__(8) __half h[4];
        h[0] = __float2half_rn(v.x); h[1] = __float2half_rn(v.y);
        h[2] = __float2half_rn(v.z); h[3] = __float2half_rn(v.w);
        if (s < 3) ((uint2*)wqkv)[s * n4 + i] = *(uint2*)h;
        else       ((uint2*)wo)[i] = *(uint2*)h;
    }
}

// ------- fused short conv (K=4) + silu + q/k l2norm; block = (t, h) --------
__global__ __launch_bounds__(256) void convnorm_kernel(const float* __restrict__ qkvlin,
                                                       const float* __restrict__ wq,
                                                       const float* __restrict__ wk,
                                                       const float* __restrict__ wv,
                                                       float* __restrict__ qb,
                                                       float* __restrict__ kb,
                                                       float* __restrict__ vb) {
    int row = blockIdx.x;
    int t = row >> 2, h = row & 3;
    int d = threadIdx.x;
    int c = h * DHEAD + d;

    float aq = 0.f, ak = 0.f, av = 0.f;
#pragma unroll
    for (int j = 0; j < 4; j++) {
        int tt = t + j - 3;
        if (tt >= 0) {
            const float* rp = qkvlin + (size_t)tt * NQKV;
            aq = fmaf(rp[c], wq[c * 4 + j], aq);
            ak = fmaf(rp[DMODEL + c], wk[c * 4 + j], ak);
            av = fmaf(rp[2 * DMODEL + c], wv[c * 4 + j], av);
        }
    }
    float qv = aq / (1.f + expf(-aq));
    float kv = ak / (1.f + expf(-ak));
    float vv = av / (1.f + expf(-av));

    float sq = qv * qv, sk = kv * kv;
#pragma unroll
    for (int off = 16; off; off >>= 1) {
        sq += __shfl_xor_sync(0xffffffffu, sq, off);
        sk += __shfl_xor_sync(0xffffffffu, sk, off);
    }
    __shared__ float red[2][8];
    int warp = d >> 5, lane = d & 31;
    if (lane == 0) { red[0][warp] = sq; red[1][warp] = sk; }
    __syncthreads();
    float ssq = 0.f, ssk = 0.f;
#pragma unroll
    for (int i = 0; i < 8; i++) { ssq += red[0][i]; ssk += red[1][i]; }

    size_t o = (size_t)t * DMODEL + c;
    qb[o] = qv * rsqrtf(ssq + 1e-6f);
    kb[o] = kv * rsqrtf(ssk + 1e-6f);
    vb[o] = vv;
}

// ---------------- beta (sigmoid) + gate probs ------------------------------
__global__ void beta_gate_kernel(const float* __restrict__ x,
                                 const float* __restrict__ Wb,
                                 const float* __restrict__ gate_w,
                                 const float* __restrict__ gate_b,
                                 const float* __restrict__ log_temp,
                                 const float* __restrict__ eps_param,
                                 float* __restrict__ beta_out,
                                 float* __restrict__ probs_out) {
    int t = blockIdx.x;
    __shared__ float sx[DMODEL];
    __shared__ float sdot[24];
    int tid = threadIdx.x;
    for (int i = tid; i < DMODEL; i += 256) sx[i] = x[t * DMODEL + i];
    __syncthreads();
    int warp = tid >> 5, lane = tid & 31;
    for (int o = warp; o < 24; o += 8) {
        const float* wrow = (o < 4) ? (Wb + o * DMODEL) : (gate_w + (o - 4) * DMODEL);
        float s = 0.f;
        for (int i = lane; i < DMODEL; i += 32) s += sx[i] * wrow[i];
#pragma unroll
        for (int off = 16; off; off >>= 1) s += __shfl_xor_sync(0xffffffffu, s, off);
        if (lane == 0) sdot[o] = s;
    }
    __syncthreads();
    if (tid < NH) {
        int h = tid;
        beta_out[t * NH + h] = 1.f / (1.f + expf(-sdot[h]));
        float temp = expf(log_temp[h]);
        float lg[5], mx = -1e30f;
#pragma unroll
        for (int p = 0; p < 5; p++) {
            lg[p] = (sdot[4 + h * 5 + p] + gate_b[h * 5 + p]) / temp;
            mx = fmaxf(mx, lg[p]);
        }
        float se = 0.f;
#pragma unroll
        for (int p = 0; p < 5; p++) { lg[p] = expf(lg[p] - mx); se += lg[p]; }
        float eps = fminf(fmaxf(eps_param[h], 0.f), 0.2f);
#pragma unroll
        for (int p = 0; p < 5; p++)
            probs_out[(t * NH + h) * 5 + p] = lg[p] / se * (1.f - 5.f * eps) + eps;
    }
}

// ---------------- per-chunk UT transform (parallel over chunks) ------------
#define CP_SMEM_FLOATS (2 * 32 * 260 + 2 * 32 * 33 + 32)
__global__ __launch_bounds__(256) void chunk_prep_kernel(const float* __restrict__ q,
                                                         const float* __restrict__ k,
                                                         const float* __restrict__ v,
                                                         const float* __restrict__ beta,
                                                         float* __restrict__ gu,
                                                         float* __restrict__ gw,
                                                         float* __restrict__ gattn) {
    extern __shared__ float smemf[];
    float (*sk)[260] = (float (*)[260])smemf;
    float (*sx)[260] = (float (*)[260])(smemf + 32 * 260);
    float (*sA)[33]  = (float (*)[33])(smemf + 2 * 32 * 260);
    float (*sT)[33]  = (float (*)[33])(smemf + 2 * 32 * 260 + 32 * 33);
    float* sbeta     = smemf + 2 * 32 * 260 + 2 * 32 * 33;

    int hb = blockIdx.x;
    int h = hb >> 6, ch = hb & 63;
    int t0 = ch * CSZ;
    int tid = threadIdx.x;

#pragma unroll
    for (int it = 0; it < 8; it++) {
        int i4 = tid + it * 256;
        int row = i4 >> 6, d4 = (i4 & 63) << 2;
        *(float4*)&sk[row][d4] =
            *(const float4*)(k + (size_t)(t0 + row) * DMODEL + h * DHEAD + d4);
    }
    if (tid < CSZ) sbeta[tid] = beta[(t0 + tid) * NH + h];
    __syncthreads();

#pragma unroll
    for (int p = tid; p < CSZ * CSZ; p += 256) {
        int i = p >> 5, j = p & 31;
        float a = 0.f;
        if (j < i) {
            float s = 0.f;
#pragma unroll 16
            for (int d4 = 0; d4 < DHEAD; d4 += 4) {
                float4 xx = *(const float4*)&sk[i][d4];
                float4 yy = *(const float4*)&sk[j][d4];
                s = fmaf(xx.x, yy.x, fmaf(xx.y, yy.y,
                    fmaf(xx.z, yy.z, fmaf(xx.w, yy.w, s))));
            }
            a = -sbeta[i] * s;
        }
        sA[i][j] = a;
    }
    __syncthreads();

    if (tid < 32) {
        int col = tid;
        for (int i = 0; i < CSZ; i++) {
            float tv = (col == i) ? 1.f : 0.f;
            for (int j = 0; j < i; j++) tv += sA[i][j] * sT[j][col];
            sT[i][col] = tv;
            __syncwarp();
        }
    }
    __syncthreads();

#pragma unroll
    for (int it = 0; it < 8; it++) {
        int i4 = tid + it * 256;
        int row = i4 >> 6, d4 = (i4 & 63) << 2;
        float4 vv = *(const float4*)(v + (size_t)(t0 + row) * DMODEL + h * DHEAD + d4);
        float bb = sbeta[row];
        vv.x *= bb; vv.y *= bb; vv.z *= bb; vv.w *= bb;
        *(float4*)&sx[row][d4] = vv;
    }
    __syncthreads();

    {
        int d = tid;
        float acc[32];
#pragma unroll
        for (int i = 0; i < 32; i++) acc[i] = 0.f;
#pragma unroll
        for (int j = 0; j < 32; j++) {
            float xv = sx[j][d];
#pragma unroll
            for (int i = j; i < 32; i++) acc[i] = fmaf(sT[i][j], xv, acc[i]);
        }
#pragma unroll
        for (int i = 0; i < 32; i++)
            gu[(t0 + i) * DMODEL + h * DHEAD + d] = acc[i];
#pragma unroll
        for (int i = 0; i < 32; i++) acc[i] = 0.f;
#pragma unroll
        for (int j = 0; j < 32; j++) {
            float xv = sbeta[j] * sk[j][d];
#pragma unroll
            for (int i = j; i < 32; i++) acc[i] = fmaf(sT[i][j], xv, acc[i]);
        }
#pragma unroll
        for (int i = 0; i < 32; i++)
            gw[(t0 + i) * DMODEL + h * DHEAD + d] = acc[i];
    }
    __syncthreads();

#pragma unroll
    for (int it = 0; it < 8; it++) {
        int i4 = tid + it * 256;
        int row = i4 >> 6, d4 = (i4 & 63) << 2;
        *(float4*)&sx[row][d4] =
            *(const float4*)(q + (size_t)(t0 + row) * DMODEL + h * DHEAD + d4);
    }
    __syncthreads();
#pragma unroll
    for (int p = tid; p < CSZ * CSZ; p += 256) {
        int i = p >> 5, j = p & 31;
        float a = 0.f;
        if (j <= i) {
            float s = 0.f;
#pragma unroll 16
            for (int d4 = 0; d4 < DHEAD; d4 += 4) {
                float4 xx = *(const float4*)&sx[i][d4];
                float4 yy = *(const float4*)&sk[j][d4];
                s = fmaf(xx.x, yy.x, fmaf(xx.y, yy.y,
                    fmaf(xx.z, yy.z, fmaf(xx.w, yy.w, s))));
            }
            a = s;
        }
        gattn[(hb * CSZ + i) * CSZ + j] = a;
    }
}

// ---------------- sequential chunk scan, cp.async double-buffered ----------
#define SD_TILE   (32 * 260)
#define SD_BUF    (3 * SD_TILE)
#define SD_SC     (2 * SD_BUF)
#define SD_SU     (SD_SC + 8 * 260)
#define SD_SATT   (SD_SU + 2 * 256)
#define SD_SUA    (SD_SATT + 2 * 1024)
#define SCAN_SMEM_FLOATS (SD_SUA + 256)
__global__ __launch_bounds__(256) void delta_scan_kernel(const float* __restrict__ q,
                                                         const float* __restrict__ k,
                                                         const float* __restrict__ w,
                                                         const float* __restrict__ u,
                                                         const float* __restrict__ attn,
                                                         float* __restrict__ dout) {
    extern __shared__ float smemf[];
    unsigned sb;
    asm("{ .reg .u64 t; cvta.to.shared.u64 t, %1; cvt.u32.u64 %0, t; }"
        : "=r"(sb) : "l"(smemf));

    int b = blockIdx.x;
    int h = b >> 5, sl = b & 31;
    int tid = threadIdx.x;
    int r = tid >> 3, c = tid & 7;
    int cbase = h * DHEAD + sl * 8;

#define SD_ISSUE(ch, bf)                                                            \
    do {                                                                            \
        int t0i = (ch) * CSZ;                                                       \
        unsigned qo = sb + ((bf) * SD_BUF) * 4;                                     \
        _Pragma("unroll")                                                           \
        for (int it = 0; it < 8; it++) {                                            \
            int i4 = tid + it * 256;                                                \
            int row = i4 >> 6, d4 = (i4 & 63) << 2;                                 \
            size_t gidx = (size_t)(t0i + row) * DMODEL + h * DHEAD + d4;            \
            unsigned so = qo + (row * 260 + d4) * 4;                                \
            cp16(so, q + gidx);                                                     \
            cp16(so + SD_TILE * 4, k + gidx);                                       \
            cp16(so + 2 * SD_TILE * 4, w + gidx);                                   \
        }                                                                           \
        cp4(sb + (SD_SU + (bf) * 256 + tid) * 4,                                    \
            u + (size_t)(t0i + r) * DMODEL + cbase + c);                            \
        cp16(sb + (SD_SATT + (bf) * 1024 + tid * 4) * 4,                            \
             attn + (size_t)(h * NCHUNK + (ch)) * 1024 + tid * 4);                  \
        asm volatile("cp.async.commit_group;" ::: "memory");                        \
    } while (0)

    float Sreg[8];
#pragma unroll
    for (int i = 0; i < 8; i++) Sreg[i] = 0.f;

    SD_ISSUE(0, 0);
    int buf = 0;
    for (int ch = 0; ch < NCHUNK; ch++) {
        if (ch + 1 < NCHUNK) {
            SD_ISSUE(ch + 1, buf ^ 1);
            asm volatile("cp.async.wait_group 1;" ::: "memory");
        } else {
            asm volatile("cp.async.wait_group 0;" ::: "memory");
        }
#pragma unroll
        for (int i = 0; i < 8; i++) smemf[SD_SC + i * 260 + tid] = Sreg[i];
        __syncthreads();

        const float* sq  = smemf + buf * SD_BUF;
        const float* skk = sq + SD_TILE;
        const float* sw  = sq + 2 * SD_TILE;
        const float* su  = smemf + SD_SU + buf * 256;
        const float* satt = smemf + SD_SATT + buf * 1024;
        float* sua = smemf + SD_SUA;

        float au = su[tid], ao = 0.f;
#pragma unroll 8
        for (int d4 = 0; d4 < DHEAD; d4 += 4) {
            float4 sv = *(const float4*)&smemf[SD_SC + c * 260 + d4];
            float4 wv = *(const float4*)&sw[r * 260 + d4];
            float4 qv = *(const float4*)&sq[r * 260 + d4];
            au = fmaf(-wv.x, sv.x, au);
            au = fmaf(-wv.y, sv.y, au);
            au = fmaf(-wv.z, sv.z, au);
            au = fmaf(-wv.w, sv.w, au);
            ao = fmaf(qv.x, sv.x, ao);
            ao = fmaf(qv.y, sv.y, ao);
            ao = fmaf(qv.z, sv.z, ao);
            ao = fmaf(qv.w, sv.w, ao);
        }
        sua[tid] = au;
        __syncthreads();

#pragma unroll
        for (int j4 = 0; j4 < CSZ; j4 += 4) {
            float4 at = *(const float4*)&satt[r * CSZ + j4];
            ao = fmaf(at.x, sua[(j4 + 0) * 8 + c], ao);
            ao = fmaf(at.y, sua[(j4 + 1) * 8 + c], ao);
            ao = fmaf(at.z, sua[(j4 + 2) * 8 + c], ao);
            ao = fmaf(at.w, sua[(j4 + 3) * 8 + c], ao);
        }
        dout[(size_t)(ch * CSZ + r) * DMODEL + cbase + c] = ao;

#pragma unroll 8
        for (int j = 0; j < CSZ; j++) {
            float kv = skk[j * 260 + tid];
            float4 u0 = *(const float4*)&sua[j * 8];
            float4 u1 = *(const float4*)&sua[j * 8 + 4];
            Sreg[0] = fmaf(kv, u0.x, Sreg[0]);
            Sreg[1] = fmaf(kv, u0.y, Sreg[1]);
            Sreg[2] = fmaf(kv, u0.z, Sreg[2]);
            Sreg[3] = fmaf(kv, u0.w, Sreg[3]);
            Sreg[4] = fmaf(kv, u1.x, Sreg[4]);
            Sreg[5] = fmaf(kv, u1.y, Sreg[5]);
            Sreg[6] = fmaf(kv, u1.z, Sreg[6]);
            Sreg[7] = fmaf(kv, u1.w, Sreg[7]);
        }
        __syncthreads();
        buf ^= 1;
    }
#undef SD_ISSUE
}

// ---------------- FIR + gated mix + RMSNorm, t-tiled; fp16 hi/lo output ----
#define CT 16
#define VR (CT + 62)
#define CMB_SMEM_FLOATS (256 * 81 + 256 * 81 + 80 + 4096 + 16)
__global__ __launch_bounds__(256) void combine_kernel(const float* __restrict__ v,
                                                      const float* __restrict__ delta,
                                                      const float* __restrict__ probs,
                                                      const float* __restrict__ fs,
                                                      const float* __restrict__ fm,
                                                      const float* __restrict__ fl,
                                                      const float* __restrict__ normw,
                                                      __half* __restrict__ outh,
                                                      __half* __restrict__ outl) {
    extern __shared__ float cs[];
    float (*vsm)[81] = (float (*)[81])cs;
    float (*fsm)[81] = (float (*)[81])(cs + 256 * 81);
    float* psm = cs + 2 * 256 * 81;
    float* sqm = psm + 80;
    float* red = sqm + 4096;

    int bid = blockIdx.x;
    int h = bid & 3;
    int tt0 = (bid >> 2) * CT;
    int tid = threadIdx.x;
    int d = tid;

    const float* flh = fl + h * 256 * 63;
    for (int f = tid; f < 256 * 63; f += 256) {
        int dd = f / 63;
        fsm[dd][f - dd * 63] = flh[f];
    }
    const float* fmh = fm + h * 256 * 15;
    for (int f = tid; f < 256 * 15; f += 256) {
        int dd = f / 15;
        fsm[dd][63 + f - dd * 15] = fmh[f];
    }
    const float* fsh = fs + h * 256 * 3;
    for (int f = tid; f < 256 * 3; f += 256) {
        int dd = f / 3;
        fsm[dd][78 + f - dd * 3] = fsh[f];
    }
    if (tid < CT * 5)
        psm[tid] = probs[(tt0 * NH + h) * 5 + (tid / 5) * (NH * 5) + (tid % 5)];
    for (int L = 0; L < VR; L++) {
        int tt = tt0 - 62 + L;
        vsm[tid][L] = (tt >= 0) ? v[(size_t)tt * DMODEL + h * DHEAD + tid] : 0.f;
    }
    __syncthreads();

    float aL[CT], aM[CT], aS[CT];
#pragma unroll
    for (int t = 0; t < CT; t++) { aL[t] = 0.f; aM[t] = 0.f; aS[t] = 0.f; }

    for (int kk = 0; kk < 63; kk++) {
        float fv = fsm[d][kk];
#pragma unroll
        for (int t = 0; t < CT; t++) aL[t] = fmaf(vsm[d][kk + t], fv, aL[t]);
    }
#pragma unroll
    for (int kk = 0; kk < 15; kk++) {
        float fv = fsm[d][63 + kk];
#pragma unroll
        for (int t = 0; t < CT; t++) aM[t] = fmaf(vsm[d][48 + kk + t], fv, aM[t]);
    }
#pragma unroll
    for (int kk = 0; kk < 3; kk++) {
        float fv = fsm[d][78 + kk];
#pragma unroll
        for (int t = 0; t < CT; t++) aS[t] = fmaf(vsm[d][60 + kk + t], fv, aS[t]);
    }

    float mixv[CT];
#pragma unroll
    for (int t = 0; t < CT; t++) {
        float dlv = delta[(size_t)(tt0 + t) * DMODEL + h * DHEAD + d];
        const float* pb = psm + t * 5;
        float vcur = vsm[d][62 + t];
        mixv[t] = pb[0] * aS[t] + pb[1] * aM[t] + pb[2] * aL[t] +
                  pb[3] * dlv + pb[4] * vcur;
        sqm[t * 256 + d] = mixv[t] * mixv[t];
    }
    __syncthreads();

    int lane = tid & 31, warp = tid >> 5;
#pragma unroll
    for (int tt = warp; tt < CT; tt += 8) {
        float s = 0.f;
#pragma unroll
        for (int i = lane; i < 256; i += 32) s += sqm[tt * 256 + i];
#pragma unroll
        for (int off = 16; off; off >>= 1) s += __shfl_xor_sync(0xffffffffu, s, off);
        if (lane == 0) red[tt] = s;
    }
    __syncthreads();

    float nw = normw[d];
#pragma unroll
    for (int t = 0; t < CT; t++) {
        float val = mixv[t] * rsqrtf(red[t] * (1.f / 256.f) + 1e-5f) * nw;
        __half hv = __float2half_rn(val);
        size_t o = (size_t)(tt0 + t) * DMODEL + h * DHEAD + d;
        outh[o] = hv;
        outl[o] = __float2half_rn(val - __half2float(hv));
    }
}

// ---------------- launch ---------------------------------------------------
extern "C" void kernel_launch(void* const* d_in, const int* in_sizes, int n_in,
                              void* d_out, int out_size) {
    const float* x       = (const float*)d_in[0];
    const float* Wq      = (const float*)d_in[1];
    const float* Wk      = (const float*)d_in[2];
    const float* Wv      = (const float*)d_in[3];
    const float* Wb      = (const float*)d_in[4];
    const float* conv_q  = (const float*)d_in[5];
    const float* conv_k  = (const float*)d_in[6];
    const float* conv_v  = (const float*)d_in[7];
    const float* fir_s   = (const float*)d_in[8];
    const float* fir_m   = (const float*)d_in[9];
    const float* fir_l   = (const float*)d_in[10];
    const float* gate_w  = (const float*)d_in[11];
    const float* gate_b  = (const float*)d_in[12];
    const float* log_tmp = (const float*)d_in[13];
    const float* eps_p   = (const float*)d_in[14];
    const float* norm_w  = (const float*)d_in[15];
    const float* Wo      = (const float*)d_in[16];
    float* out = (float*)d_out;

    float *qkvlin, *qb, *kb, *vb, *ub, *wb, *db, *betab, *probsb, *attnb;
    cudaGetSymbolAddress((void**)&qkvlin, g_qkvlin);
    cudaGetSymbolAddress((void**)&qb,    g_q);
    cudaGetSymbolAddress((void**)&kb,    g_k);
    cudaGetSymbolAddress((void**)&vb,    g_v);
    cudaGetSymbolAddress((void**)&ub,    g_u);
    cudaGetSymbolAddress((void**)&wb,    g_w);
    cudaGetSymbolAddress((void**)&db,    g_delta);
    cudaGetSymbolAddress((void**)&betab, g_beta);
    cudaGetSymbolAddress((void**)&probsb, g_probs);
    cudaGetSymbolAddress((void**)&attnb, g_attn);

    __half *xh, *xl, *wqkv, *wo, *mixh, *mixl;
    cudaGetSymbolAddress((void**)&xh, g_xh);
    cudaGetSymbolAddress((void**)&xl, g_xl);
    cudaGetSymbolAddress((void**)&wqkv, g_wqkv);
    cudaGetSymbolAddress((void**)&wo, g_wo);
    cudaGetSymbolAddress((void**)&mixh, g_mixh);
    cudaGetSymbolAddress((void**)&mixl, g_mixl);

    cudaFuncSetAttribute(hgemm_nt, cudaFuncAttributeMaxDynamicSharedMemorySize, HG_SMEM);
    cudaFuncSetAttribute(chunk_prep_kernel, cudaFuncAttributeMaxDynamicSharedMemorySize,
                         CP_SMEM_FLOATS * 4);
    cudaFuncSetAttribute(delta_scan_kernel, cudaFuncAttributeMaxDynamicSharedMemorySize,
                         SCAN_SMEM_FLOATS * 4);
    cudaFuncSetAttribute(combine_kernel, cudaFuncAttributeMaxDynamicSharedMemorySize,
                         CMB_SMEM_FLOATS * 4);

    int nX4 = SEQ * DMODEL / 4;
    int nW4 = DMODEL * DMODEL / 4;

    split_kernel<<<(nX4 + 255) / 256, 256>>>(x, xh, xl, nX4);                 // 0
    wsplit_kernel<<<(nW4 + 255) / 256, 256>>>(Wq, Wk, Wv, Wo, wqkv, wo);      // 1
    beta_gate_kernel<<<SEQ, 256>>>(x, Wb, gate_w, gate_b, log_tmp, eps_p,
                                   betab, probsb);                            // 2
    dim3 tg3(NQKV / 128, SEQ / 128);                                          // (24,16)
    hgemm_nt<<<tg3, 256, HG_SMEM>>>(xh, xl, wqkv, qkvlin, SEQ, NQKV, DMODEL); // 3 (ncu)
    convnorm_kernel<<<SEQ * NH, 256>>>(qkvlin, conv_q, conv_k, conv_v,
                                       qb, kb, vb);                           // 4
    chunk_prep_kernel<<<NH * NCHUNK, 256, CP_SMEM_FLOATS * 4>>>(qb, kb, vb, betab,
                                                                ub, wb, attnb);
    delta_scan_kernel<<<NH * 32, 256, SCAN_SMEM_FLOATS * 4>>>(qb, kb, wb, ub,
                                                              attnb, db);
    combine_kernel<<<(SEQ / CT) * NH, 256, CMB_SMEM_FLOATS * 4>>>(
        vb, db, probsb, fir_s, fir_m, fir_l, norm_w, mixh, mixl);
    dim3 tg1(DMODEL / 128, SEQ / 128);                                        // (8,16)
    hgemm_nt<<<tg1, 256, HG_SMEM>>>(mixh, mixl, wo, out, SEQ, DMODEL, DMODEL);
}